// round 10
// baseline (speedup 1.0000x reference)
#include <cuda_runtime.h>
#include <cuda.h>
#include <cuda_fp16.h>
#include <math.h>
#include <stdint.h>

// Problem constants
#define NUM_HEADS 16
#define HEAD_SIZE 128
#define HIDDEN    2048
#define ROT       16
#define BATCH     4
#define SEQ       1024
#define TOTAL     4096
#define QKV_N     6144

// -------- device scratch --------
__device__ __half g_qkvh[(size_t)TOTAL * QKV_N];       // QKV GEMM output (half)
__device__ __half g_qh[(size_t)TOTAL * HIDDEN];        // Q half, pre-scaled, [B,H,S,D]
__device__ __half g_kh[(size_t)TOTAL * HIDDEN];        // K half, [B,H,S,D]
__device__ float  g_v[(size_t)TOTAL * HIDDEN];         // V fp32, [B,H,S,D]
__device__ __half g_vth[(size_t)BATCH * NUM_HEADS * HEAD_SIZE * SEQ];  // V^T half [B,H,D,S]
__device__ __half g_attnh[(size_t)TOTAL * HIDDEN];     // flash output (half)
__device__ __half g_hidh[(size_t)TOTAL * HIDDEN];      // hidden states (half)
__device__ __half g_wqkvTh[(size_t)QKV_N * HIDDEN];    // W_qkv^T [N][K] half
__device__ __half g_wdenseTh[(size_t)HIDDEN * HIDDEN]; // W_dense^T [N][K] half

// ============================================================================
// helpers
// ============================================================================
__device__ __forceinline__ uint32_t smem_u32(const void* p) {
    uint32_t a;
    asm("{ .reg .u64 t; cvta.to.shared.u64 t, %1; cvt.u32.u64 %0, t; }" : "=r"(a) : "l"(p));
    return a;
}
__device__ __forceinline__ void mma_f16(float* c, const uint32_t* a, uint32_t b0, uint32_t b1) {
    asm volatile(
        "mma.sync.aligned.m16n8k16.row.col.f32.f16.f16.f32 "
        "{%0,%1,%2,%3}, {%4,%5,%6,%7}, {%8,%9}, {%0,%1,%2,%3};"
        : "+f"(c[0]), "+f"(c[1]), "+f"(c[2]), "+f"(c[3])
        : "r"(a[0]), "r"(a[1]), "r"(a[2]), "r"(a[3]), "r"(b0), "r"(b1));
}
__device__ __forceinline__ void ldsm_x4(uint32_t* r, uint32_t addr) {
    asm volatile("ldmatrix.sync.aligned.m8n8.x4.shared.b16 {%0,%1,%2,%3}, [%4];"
        : "=r"(r[0]), "=r"(r[1]), "=r"(r[2]), "=r"(r[3]) : "r"(addr));
}

// ============================================================================
// fp16 mma.sync GEMM v4: C = A[M,K] @ Bt[N,K]^T + bias
// 128x128 CTA tile, 4 warps (2x2), warp tile 64x64, K-chunk 64, 3-stage
// cp.async pipeline + REGISTER double-buffered fragments (LDSM of k-step s+1
// overlaps MMA of k-step s -> crossbar/tensor overlap, no phase convoy).
// ============================================================================
#define NSTAGE 3
#define KCH 64
#define LDH 72                            // halves per smem row (144B)
#define GEMM_STAGE (128 * LDH)            // halves per stage per matrix
#define STAGE_B (GEMM_STAGE * 2)          // bytes per stage per matrix (18432)
#define GEMM_SMEM_BYTES (NSTAGE * STAGE_B * 2)   // 110592 B

template<bool HALF_OUT>
__global__ void __launch_bounds__(128, 2) gemm_f16_v4(
    const __half* __restrict__ A, const __half* __restrict__ Bt,
    const float* __restrict__ bias, float* __restrict__ Cf,
    __half* __restrict__ Ch, int M, int N, int K)
{
    extern __shared__ __half hsm[];
    __half* As = hsm;                           // [NSTAGE][128][LDH]
    __half* Bs = hsm + NSTAGE * GEMM_STAGE;     // [NSTAGE][128][LDH]

    const int tid  = threadIdx.x;
    const int wid  = tid >> 5;        // 0..3
    const int lane = tid & 31;
    const int wm = wid >> 1;          // 0..1 : 64-row band
    const int wn = wid & 1;           // 0..1 : 64-col band
    const int qr = lane >> 2;
    const int qc = lane & 3;
    const int m0 = blockIdx.y * 128;
    const int n0 = blockIdx.x * 128;
    const int lrow = lane & 15;
    const int lcol = (lane >> 4) * 8;

    // cp.async addressing: 128 threads, each owns 8 rows (row0 + 16*it)
    const int row0 = tid >> 3;            // 0..15
    const int c8   = (tid & 7) << 3;      // 0..56
    const __half* srcA = A  + (size_t)(m0 + row0) * K + c8;
    const __half* srcB = Bt + (size_t)(n0 + row0) * K + c8;
    const uint32_t dA0 = smem_u32(As) + (uint32_t)(row0 * LDH + c8) * 2u;
    const uint32_t dB0 = smem_u32(Bs) + (uint32_t)(row0 * LDH + c8) * 2u;
    const size_t gRow = (size_t)16 * K;
    const uint32_t sRow = 16u * LDH * 2u;

    // LDSM base addresses (stage 0, k0 = 0): 4 A row-tiles, 4 B col-tiles
    uint32_t aAddr[4], bAddr[4];
#pragma unroll
    for (int mt = 0; mt < 4; ++mt)
        aAddr[mt] = smem_u32(As) + (uint32_t)((wm * 64 + mt * 16 + lrow) * LDH + lcol) * 2u;
#pragma unroll
    for (int nt2 = 0; nt2 < 4; ++nt2)
        bAddr[nt2] = smem_u32(Bs) + (uint32_t)((wn * 64 + nt2 * 16 + lrow) * LDH + lcol) * 2u;

    float acc[4][8][4];
#pragma unroll
    for (int i = 0; i < 4; ++i)
#pragma unroll
        for (int j = 0; j < 8; ++j)
#pragma unroll
            for (int k = 0; k < 4; ++k) acc[i][j][k] = 0.0f;

    auto load_chunk = [&](const __half* pA, const __half* pB, uint32_t sOff) {
#pragma unroll
        for (int it = 0; it < 8; ++it) {
            asm volatile("cp.async.cg.shared.global [%0], [%1], 16;"
                :: "r"(dA0 + sOff + it * sRow), "l"(pA + it * gRow) : "memory");
            asm volatile("cp.async.cg.shared.global [%0], [%1], 16;"
                :: "r"(dB0 + sOff + it * sRow), "l"(pB + it * gRow) : "memory");
        }
        asm volatile("cp.async.commit_group;" ::: "memory");
    };

    // register fragment buffers (double-buffered over k-steps)
    uint32_t af[2][4][4], bf[2][4][4];

    auto ld_frags = [&](int buf, uint32_t kOff) {
#pragma unroll
        for (int mt = 0; mt < 4; ++mt) ldsm_x4(af[buf][mt], aAddr[mt] + kOff);
#pragma unroll
        for (int nt2 = 0; nt2 < 4; ++nt2) ldsm_x4(bf[buf][nt2], bAddr[nt2] + kOff);
    };
    auto do_mmas = [&](int buf) {
#pragma unroll
        for (int mt = 0; mt < 4; ++mt)
#pragma unroll
            for (int nt = 0; nt < 8; ++nt)
                mma_f16(acc[mt][nt], af[buf][mt],
                        bf[buf][nt >> 1][nt & 1], bf[buf][nt >> 1][2 + (nt & 1)]);
    };

    const int NCH = K / KCH;
    load_chunk(srcA, srcB, 0);
    srcA += KCH; srcB += KCH;
    load_chunk(srcA, srcB, STAGE_B);
    srcA += KCH; srcB += KCH;

    uint32_t sC = 0;                    // compute-stage byte offset
    uint32_t sL = 2 * STAGE_B;          // next load-stage byte offset

    for (int c = 0; c < NCH; ++c) {
        if (c + 1 < NCH) { asm volatile("cp.async.wait_group 1;" ::: "memory"); }
        else             { asm volatile("cp.async.wait_group 0;" ::: "memory"); }
        __syncthreads();

        if (c + 2 < NCH) {
            load_chunk(srcA, srcB, sL);
            srcA += KCH; srcB += KCH;
            sL += STAGE_B; if (sL == NSTAGE * STAGE_B) sL = 0;
        }

        // software-pipelined k-steps: LDSM(ks+1) issued before MMA(ks)
        ld_frags(0, sC);
        ld_frags(1, sC + 32);      // 16 halves = 32 B
        do_mmas(0);
        ld_frags(0, sC + 64);
        do_mmas(1);
        ld_frags(1, sC + 96);
        do_mmas(0);
        do_mmas(1);

        sC += STAGE_B; if (sC == NSTAGE * STAGE_B) sC = 0;
    }

#pragma unroll
    for (int mt = 0; mt < 4; ++mt) {
        const int row = m0 + wm * 64 + mt * 16 + qr;
#pragma unroll
        for (int nt = 0; nt < 8; ++nt) {
            const int col = n0 + wn * 64 + nt * 8 + 2 * qc;
            const float2 bv = *(const float2*)&bias[col];
            const float v00 = acc[mt][nt][0] + bv.x, v01 = acc[mt][nt][1] + bv.y;
            const float v10 = acc[mt][nt][2] + bv.x, v11 = acc[mt][nt][3] + bv.y;
            if (HALF_OUT) {
                *(__half2*)&Ch[(size_t)row * N + col]       = __floats2half2_rn(v00, v01);
                *(__half2*)&Ch[(size_t)(row + 8) * N + col] = __floats2half2_rn(v10, v11);
            } else {
                *(float2*)&Cf[(size_t)row * N + col]       = make_float2(v00, v01);
                *(float2*)&Cf[(size_t)(row + 8) * N + col] = make_float2(v10, v11);
            }
        }
    }
}

// ============================================================================
// float -> half bulk convert
// ============================================================================
__global__ void __launch_bounds__(256) f2h_copy(
    const float* __restrict__ src, __half* __restrict__ dst, int n4)
{
    const int i = blockIdx.x * 256 + threadIdx.x;
    if (i < n4) {
        float4 v = ((const float4*)src)[i];
        ((__half2*)dst)[2 * i]     = __floats2half2_rn(v.x, v.y);
        ((__half2*)dst)[2 * i + 1] = __floats2half2_rn(v.z, v.w);
    }
}

// ============================================================================
// Transpose + half convert: dst[Ccols][R] = h(src[R][Ccols])
// ============================================================================
__global__ void __launch_bounds__(256) transpose_h(
    const float* __restrict__ src, __half* __restrict__ dst, int R, int Ccols)
{
    __shared__ float t[32][33];
    const int tx = threadIdx.x & 31;
    const int ty = threadIdx.x >> 5;
    const int c0 = blockIdx.x * 32;
    const int r0 = blockIdx.y * 32;
#pragma unroll
    for (int j = 0; j < 4; ++j)
        t[ty + 8 * j][tx] = src[(size_t)(r0 + ty + 8 * j) * Ccols + c0 + tx];
    __syncthreads();
#pragma unroll
    for (int j = 0; j < 4; ++j)
        dst[(size_t)(c0 + ty + 8 * j) * R + r0 + tx] = __float2half_rn(t[tx][ty + 8 * j]);
}

// ============================================================================
// V transpose per head: g_v [BH, S, D] -> g_vth [BH, D, S] (half)
// ============================================================================
__global__ void __launch_bounds__(256) transpose_v_h()
{
    __shared__ float t[32][33];
    const int tx = threadIdx.x & 31;
    const int ty = threadIdx.x >> 5;
    const int d0 = blockIdx.x * 32;
    const int s0 = blockIdx.y * 32;
    const int bh = blockIdx.z;
    const float* src = g_v + (size_t)bh * SEQ * HEAD_SIZE;
    __half* dst = g_vth + (size_t)bh * HEAD_SIZE * SEQ;
#pragma unroll
    for (int j = 0; j < 4; ++j)
        t[ty + 8 * j][tx] = src[(size_t)(s0 + ty + 8 * j) * HEAD_SIZE + d0 + tx];
    __syncthreads();
#pragma unroll
    for (int j = 0; j < 4; ++j)
        dst[(size_t)(d0 + ty + 8 * j) * SEQ + s0 + tx] = __float2half_rn(t[tx][ty + 8 * j]);
}

// ============================================================================
// rotary embedding + split (reads half QKV): Q (half, pre-scaled) / K / V(f32)
// ============================================================================
__global__ void __launch_bounds__(256) rope_split(
    const float* __restrict__ cosb, const float* __restrict__ sinb)
{
    const int t = blockIdx.x;
    const int b = t >> 10;
    const int s = t & 1023;
    const __half* qkv = g_qkvh + (size_t)t * QKV_N;
    const float scale = 0.08838834764831845f;   // 1/sqrt(128)

    for (int idx = threadIdx.x; idx < HIDDEN; idx += blockDim.x) {
        const int h = idx >> 7;
        const int d = idx & 127;
        const size_t src = (size_t)h * HEAD_SIZE + d;
        const size_t dst = ((size_t)(b * NUM_HEADS + h) * SEQ + s) * HEAD_SIZE + d;

        float qv = __half2float(qkv[src]);
        float kv = __half2float(qkv[src + HIDDEN]);
        float vv = __half2float(qkv[src + 2 * HIDDEN]);

        if (d < 2 * ROT) {
            if (d < ROT) {
                const float c  = cosb[t * ROT + d];
                const float sn = sinb[t * ROT + d];
                const float q2 = __half2float(qkv[src + ROT]);
                const float k2 = __half2float(qkv[src + HIDDEN + ROT]);
                qv = qv * c - q2 * sn;
                kv = kv * c - k2 * sn;
            } else {
                const int r = d - ROT;
                const float c  = cosb[t * ROT + r];
                const float sn = sinb[t * ROT + r];
                const float q1 = __half2float(qkv[src - ROT]);
                const float k1 = __half2float(qkv[src + HIDDEN - ROT]);
                qv = q1 * sn + qv * c;
                kv = k1 * sn + kv * c;
            }
        }
        g_qh[dst] = __float2half_rn(qv * scale);
        g_kh[dst] = __float2half_rn(kv);
        g_v[dst]  = vv;
    }
}

// ============================================================================
// flash attention v4 — fp16 mma + ldmatrix for score AND PV. (unchanged)
// ============================================================================
#define FQT 64
#define FKT 64
#define LDQ 136
#define LDSC 68
#define LDPH 72
#define LDVT 72

struct FlashSmem {
    __half Qs[FQT][LDQ];
    __half Ks[FKT][LDQ];
    __half Vt[HEAD_SIZE][LDVT];
    float  Sc[FQT][LDSC];
    __half Ph[FQT][LDPH];
    float m_s[FQT];
    float l_s[FQT];
    float a_s[FQT];
};

__global__ void __launch_bounds__(256) flash_f16()
{
    extern __shared__ char sraw[];
    FlashSmem& S = *reinterpret_cast<FlashSmem*>(sraw);

    const int qt = blockIdx.x;
    const int h  = blockIdx.y;
    const int b  = blockIdx.z;
    const int tid  = threadIdx.x;
    const int wid  = tid >> 5;
    const int lane = tid & 31;
    const int qr = lane >> 2;
    const int qc = lane & 3;
    const int wm = wid & 3;
    const int wn = wid >> 2;
    const int lrow = lane & 15;
    const int lcol = (lane >> 4) * 8;
    const int bh = b * NUM_HEADS + h;
    const size_t headbase = (size_t)bh * SEQ * HEAD_SIZE;

    {
        const __half* qg = g_qh + headbase + (size_t)(qt * FQT) * HEAD_SIZE;
#pragma unroll
        for (int it = 0; it < 4; ++it) {
            const int flat = it * 256 + tid;
            const int r = flat >> 4;
            const int c = (flat & 15) << 3;
            *(uint4*)&S.Qs[r][c] = *(const uint4*)(qg + (size_t)r * HEAD_SIZE + c);
        }
    }
    if (tid < FQT) { S.m_s[tid] = -1e30f; S.l_s[tid] = 0.0f; }

    float oacc[8][4];
#pragma unroll
    for (int i = 0; i < 8; ++i)
#pragma unroll
        for (int j = 0; j < 4; ++j) oacc[i][j] = 0.0f;

    const int nkt = qt + 1;
    for (int kt = 0; kt < nkt; ++kt) {
        __syncthreads();
        {
            const __half* kg = g_kh + headbase + (size_t)(kt * FKT) * HEAD_SIZE;
#pragma unroll
            for (int it = 0; it < 4; ++it) {
                const int flat = it * 256 + tid;
                const int r = flat >> 4;
                const int c = (flat & 15) << 3;
                *(uint4*)&S.Ks[r][c] = *(const uint4*)(kg + (size_t)r * HEAD_SIZE + c);
            }
            const __half* vg = g_vth + (size_t)bh * HEAD_SIZE * SEQ + kt * FKT;
#pragma unroll
            for (int it = 0; it < 4; ++it) {
                const int flat = it * 256 + tid;
                const int d = flat >> 3;
                const int s8 = (flat & 7) << 3;
                *(uint4*)&S.Vt[d][s8] = *(const uint4*)(vg + (size_t)d * SEQ + s8);
            }
        }
        __syncthreads();

        // score
        {
            float sacc[4][4];
#pragma unroll
            for (int i = 0; i < 4; ++i)
#pragma unroll
                for (int j = 0; j < 4; ++j) sacc[i][j] = 0.0f;
            const int m0 = wm * 16;
            const int n0 = wn * 32;
            const uint32_t aBase = smem_u32(&S.Qs[m0 + lrow][lcol]);
            const uint32_t bBase0 = smem_u32(&S.Ks[n0 + lrow][lcol]);
            const uint32_t bBase1 = smem_u32(&S.Ks[n0 + 16 + lrow][lcol]);
#pragma unroll
            for (int ks = 0; ks < 8; ++ks) {
                const uint32_t kOff = (uint32_t)(ks * 16 * 2);
                uint32_t af[4], bf0[4], bf1[4];
                ldsm_x4(af, aBase + kOff);
                ldsm_x4(bf0, bBase0 + kOff);
                ldsm_x4(bf1, bBase1 + kOff);
                mma_f16(sacc[0], af, bf0[0], bf0[2]);
                mma_f16(sacc[1], af, bf0[1], bf0[3]);
                mma_f16(sacc[2], af, bf1[0], bf1[2]);
                mma_f16(sacc[3], af, bf1[1], bf1[3]);
            }
#pragma unroll
            for (int nt = 0; nt < 4; ++nt) {
                const int col = n0 + nt * 8 + 2 * qc;
                *(float2*)&S.Sc[m0 + qr    ][col] = make_float2(sacc[nt][0], sacc[nt][1]);
                *(float2*)&S.Sc[m0 + qr + 8][col] = make_float2(sacc[nt][2], sacc[nt][3]);
            }
        }
        __syncthreads();

        // online softmax
        {
            const int row = tid >> 2;
            const int sub = tid & 3;
            const int sq  = qt * FQT + row;
            const int c0  = sub * 16;
            float sv[16];
            float mx = -1e30f;
#pragma unroll
            for (int jj = 0; jj < 16; ++jj) {
                const int cg = kt * FKT + c0 + jj;
                float s = S.Sc[row][c0 + jj];
                s = (cg > sq) ? -1e30f : s;
                sv[jj] = s;
                mx = fmaxf(mx, s);
            }
            mx = fmaxf(mx, __shfl_xor_sync(0xffffffffu, mx, 1));
            mx = fmaxf(mx, __shfl_xor_sync(0xffffffffu, mx, 2));
            const float m_old = S.m_s[row];
            const float m_new = fmaxf(m_old, mx);
            float sum = 0.0f;
#pragma unroll
            for (int jj = 0; jj < 16; jj += 2) {
                const float p0 = __expf(sv[jj]     - m_new);
                const float p1 = __expf(sv[jj + 1] - m_new);
                sum += p0 + p1;
                *(__half2*)&S.Ph[row][c0 + jj] = __floats2half2_rn(p0, p1);
            }
            sum += __shfl_xor_sync(0xffffffffu, sum, 1);
            sum += __shfl_xor_sync(0xffffffffu, sum, 2);
            __syncwarp();
            if (sub == 0) {
                const float alpha = __expf(m_old - m_new);
                S.a_s[row] = alpha;
                S.m_s[row] = m_new;
                S.l_s[row] = S.l_s[row] * alpha + sum;
            }
        }
        __syncthreads();

        // PV
        {
            const int m0 = wm * 16;
            const int n0 = wn * 64;
            const float al0 = S.a_s[m0 + qr];
            const float al1 = S.a_s[m0 + qr + 8];
#pragma unroll
            for (int nt = 0; nt < 8; ++nt) {
                oacc[nt][0] *= al0; oacc[nt][1] *= al0;
                oacc[nt][2] *= al1; oacc[nt][3] *= al1;
            }
            const uint32_t aBase = smem_u32(&S.Ph[m0 + lrow][lcol]);
            uint32_t bBase[4];
#pragma unroll
            for (int nt2 = 0; nt2 < 4; ++nt2)
                bBase[nt2] = smem_u32(&S.Vt[n0 + nt2 * 16 + lrow][lcol]);
#pragma unroll
            for (int ks = 0; ks < 4; ++ks) {
                const uint32_t kOff = (uint32_t)(ks * 16 * 2);
                uint32_t af[4];
                ldsm_x4(af, aBase + kOff);
#pragma unroll
                for (int nt2 = 0; nt2 < 4; ++nt2) {
                    uint32_t bf[4];
                    ldsm_x4(bf, bBase[nt2] + kOff);
                    mma_f16(oacc[nt2 * 2    ], af, bf[0], bf[2]);
                    mma_f16(oacc[nt2 * 2 + 1], af, bf[1], bf[3]);
                }
            }
        }
    }

    // epilogue
    {
        const int m0 = wm * 16;
        const int n0 = wn * 64;
        const int t0 = b * SEQ + qt * FQT;
        const float inv0 = 1.0f / S.l_s[m0 + qr];
        const float inv1 = 1.0f / S.l_s[m0 + qr + 8];
#pragma unroll
        for (int nt = 0; nt < 8; ++nt) {
            const int col = h * HEAD_SIZE + n0 + nt * 8 + 2 * qc;
            *(__half2*)&g_attnh[(size_t)(t0 + m0 + qr    ) * HIDDEN + col] =
                __floats2half2_rn(oacc[nt][0] * inv0, oacc[nt][1] * inv0);
            *(__half2*)&g_attnh[(size_t)(t0 + m0 + qr + 8) * HIDDEN + col] =
                __floats2half2_rn(oacc[nt][2] * inv1, oacc[nt][3] * inv1);
        }
    }
}

// ============================================================================
// launch
// ============================================================================
extern "C" void kernel_launch(void* const* d_in, const int* in_sizes, int n_in,
                              void* d_out, int out_size)
{
    const float* hidden  = (const float*)d_in[0];
    const float* cosb    = (const float*)d_in[1];
    const float* sinb    = (const float*)d_in[2];
    const float* W_qkv   = (const float*)d_in[3];
    const float* b_qkv   = (const float*)d_in[4];
    const float* W_dense = (const float*)d_in[5];
    const float* b_dense = (const float*)d_in[6];
    float* out = (float*)d_out;

    __half *qkvh_ptr, *attnh_ptr, *hidh_ptr, *wqkvTh_ptr, *wdenseTh_ptr;
    cudaGetSymbolAddress((void**)&qkvh_ptr, g_qkvh);
    cudaGetSymbolAddress((void**)&attnh_ptr, g_attnh);
    cudaGetSymbolAddress((void**)&hidh_ptr, g_hidh);
    cudaGetSymbolAddress((void**)&wqkvTh_ptr, g_wqkvTh);
    cudaGetSymbolAddress((void**)&wdenseTh_ptr, g_wdenseTh);

    cudaFuncSetAttribute(flash_f16, cudaFuncAttributeMaxDynamicSharedMemorySize,
                         (int)sizeof(FlashSmem));
    cudaFuncSetAttribute(gemm_f16_v4<true>,  cudaFuncAttributeMaxDynamicSharedMemorySize,
                         GEMM_SMEM_BYTES);
    cudaFuncSetAttribute(gemm_f16_v4<false>, cudaFuncAttributeMaxDynamicSharedMemorySize,
                         GEMM_SMEM_BYTES);

    // 0) operand prep (half)
    {
        const int n4 = TOTAL * HIDDEN / 4;
        f2h_copy<<<(n4 + 255) / 256, 256>>>(hidden, hidh_ptr, n4);
        transpose_h<<<dim3(QKV_N / 32, HIDDEN / 32), 256>>>(W_qkv, wqkvTh_ptr, HIDDEN, QKV_N);
        transpose_h<<<dim3(HIDDEN / 32, HIDDEN / 32), 256>>>(W_dense, wdenseTh_ptr, HIDDEN, HIDDEN);
    }
    // 1) QKV projection (fp16 mma v4: 64x64 warp tile + frag pipeline)
    gemm_f16_v4<true><<<dim3(QKV_N / 128, TOTAL / 128), 128, GEMM_SMEM_BYTES>>>(
        hidh_ptr, wqkvTh_ptr, b_qkv, nullptr, qkvh_ptr, TOTAL, QKV_N, HIDDEN);
    // 2) rotary + split
    rope_split<<<TOTAL, 256>>>(cosb, sinb);
    // 2b) V transpose per head (half)
    transpose_v_h<<<dim3(HEAD_SIZE / 32, SEQ / 32, BATCH * NUM_HEADS), 256>>>();
    // 3) causal flash attention (fp16 tensor-core)
    flash_f16<<<dim3(SEQ / FQT, NUM_HEADS, BATCH), 256, sizeof(FlashSmem)>>>();
    // 4) dense projection (fp16 mma v4, fp32 output)
    gemm_f16_v4<false><<<dim3(HIDDEN / 128, TOTAL / 128), 128, GEMM_SMEM_BYTES>>>(
        attnh_ptr, wdenseTh_ptr, b_dense, out, nullptr, TOTAL, HIDDEN, HIDDEN);
}

// round 11
// speedup vs baseline: 1.0688x; 1.0688x over previous
#include <cuda_runtime.h>
#include <cuda.h>
#include <cuda_fp16.h>
#include <math.h>
#include <stdint.h>

// Problem constants
#define NUM_HEADS 16
#define HEAD_SIZE 128
#define HIDDEN    2048
#define ROT       16
#define BATCH     4
#define SEQ       1024
#define TOTAL     4096
#define QKV_N     6144

// -------- device scratch --------
__device__ __half g_qkvh[(size_t)TOTAL * QKV_N];       // QKV GEMM output (half)
__device__ __half g_qh[(size_t)TOTAL * HIDDEN];        // Q half, pre-scaled, [B,H,S,D]
__device__ __half g_kh[(size_t)TOTAL * HIDDEN];        // K half, [B,H,S,D]
__device__ __half g_vh[(size_t)TOTAL * HIDDEN];        // V half, [B,H,S,D]
__device__ __half g_vth[(size_t)BATCH * NUM_HEADS * HEAD_SIZE * SEQ];  // V^T half [B,H,D,S]
__device__ __half g_attnh[(size_t)TOTAL * HIDDEN];     // flash output (half)
__device__ __half g_hidh[(size_t)TOTAL * HIDDEN];      // hidden states (half)
__device__ __half g_wqkvTh[(size_t)QKV_N * HIDDEN];    // W_qkv^T [N][K] half
__device__ __half g_wdenseTh[(size_t)HIDDEN * HIDDEN]; // W_dense^T [N][K] half

// ============================================================================
// helpers
// ============================================================================
__device__ __forceinline__ uint32_t smem_u32(const void* p) {
    uint32_t a;
    asm("{ .reg .u64 t; cvta.to.shared.u64 t, %1; cvt.u32.u64 %0, t; }" : "=r"(a) : "l"(p));
    return a;
}
__device__ __forceinline__ void mma_f16(float* c, const uint32_t* a, uint32_t b0, uint32_t b1) {
    asm volatile(
        "mma.sync.aligned.m16n8k16.row.col.f32.f16.f16.f32 "
        "{%0,%1,%2,%3}, {%4,%5,%6,%7}, {%8,%9}, {%0,%1,%2,%3};"
        : "+f"(c[0]), "+f"(c[1]), "+f"(c[2]), "+f"(c[3])
        : "r"(a[0]), "r"(a[1]), "r"(a[2]), "r"(a[3]), "r"(b0), "r"(b1));
}
__device__ __forceinline__ void ldsm_x4(uint32_t* r, uint32_t addr) {
    asm volatile("ldmatrix.sync.aligned.m8n8.x4.shared.b16 {%0,%1,%2,%3}, [%4];"
        : "=r"(r[0]), "=r"(r[1]), "=r"(r[2]), "=r"(r[3]) : "r"(addr));
}
__device__ __forceinline__ uint32_t pack_h2(float a, float b) {
    __half2 h = __floats2half2_rn(a, b);
    return *(uint32_t*)&h;
}

// ============================================================================
// fp16 mma.sync GEMM v3 (reverted round-8/9 best): C = A[M,K] @ Bt[N,K]^T + b
// 128x128 CTA tile, 8 warps (2x4), warp tile 64x32, K-chunk 64, 3-stage,
// single barrier per chunk.
// ============================================================================
#define NSTAGE 3
#define KCH 64
#define LDH 72
#define GEMM_STAGE (128 * LDH)
#define STAGE_B (GEMM_STAGE * 2)
#define GEMM_SMEM_BYTES (NSTAGE * STAGE_B * 2)   // 110592 B

template<bool HALF_OUT>
__global__ void __launch_bounds__(256, 2) gemm_f16_v3(
    const __half* __restrict__ A, const __half* __restrict__ Bt,
    const float* __restrict__ bias, float* __restrict__ Cf,
    __half* __restrict__ Ch, int M, int N, int K)
{
    extern __shared__ __half hsm[];
    __half* As = hsm;
    __half* Bs = hsm + NSTAGE * GEMM_STAGE;

    const int tid  = threadIdx.x;
    const int wid  = tid >> 5;
    const int lane = tid & 31;
    const int wm = wid >> 2;
    const int wn = wid & 3;
    const int qr = lane >> 2;
    const int qc = lane & 3;
    const int m0 = blockIdx.y * 128;
    const int n0 = blockIdx.x * 128;
    const int lrow = lane & 15;
    const int lcol = (lane >> 4) * 8;

    const int row0 = tid >> 3;
    const int c8   = (tid & 7) << 3;
    const __half* srcA = A  + (size_t)(m0 + row0) * K + c8;
    const __half* srcB = Bt + (size_t)(n0 + row0) * K + c8;
    const uint32_t dA0 = smem_u32(As) + (uint32_t)(row0 * LDH + c8) * 2u;
    const uint32_t dB0 = smem_u32(Bs) + (uint32_t)(row0 * LDH + c8) * 2u;
    const size_t gRow = (size_t)32 * K;
    const uint32_t sRow = 32u * LDH * 2u;

    uint32_t aAddr[4], bAddr[2];
#pragma unroll
    for (int mt = 0; mt < 4; ++mt)
        aAddr[mt] = smem_u32(As) + (uint32_t)((wm * 64 + mt * 16 + lrow) * LDH + lcol) * 2u;
#pragma unroll
    for (int nt2 = 0; nt2 < 2; ++nt2)
        bAddr[nt2] = smem_u32(Bs) + (uint32_t)((wn * 32 + nt2 * 16 + lrow) * LDH + lcol) * 2u;

    float acc[4][4][4];
#pragma unroll
    for (int i = 0; i < 4; ++i)
#pragma unroll
        for (int j = 0; j < 4; ++j)
#pragma unroll
            for (int k = 0; k < 4; ++k) acc[i][j][k] = 0.0f;

    auto load_chunk = [&](const __half* pA, const __half* pB, uint32_t sOff) {
#pragma unroll
        for (int it = 0; it < 4; ++it) {
            asm volatile("cp.async.cg.shared.global [%0], [%1], 16;"
                :: "r"(dA0 + sOff + it * sRow), "l"(pA + it * gRow) : "memory");
            asm volatile("cp.async.cg.shared.global [%0], [%1], 16;"
                :: "r"(dB0 + sOff + it * sRow), "l"(pB + it * gRow) : "memory");
        }
        asm volatile("cp.async.commit_group;" ::: "memory");
    };

    const int NCH = K / KCH;
    load_chunk(srcA, srcB, 0);
    srcA += KCH; srcB += KCH;
    load_chunk(srcA, srcB, STAGE_B);
    srcA += KCH; srcB += KCH;

    uint32_t sC = 0;
    uint32_t sL = 2 * STAGE_B;

    for (int c = 0; c < NCH; ++c) {
        if (c + 1 < NCH) { asm volatile("cp.async.wait_group 1;" ::: "memory"); }
        else             { asm volatile("cp.async.wait_group 0;" ::: "memory"); }
        __syncthreads();

        if (c + 2 < NCH) {
            load_chunk(srcA, srcB, sL);
            srcA += KCH; srcB += KCH;
            sL += STAGE_B; if (sL == NSTAGE * STAGE_B) sL = 0;
        }

#pragma unroll
        for (int ks = 0; ks < 4; ++ks) {
            const uint32_t kOff = sC + (uint32_t)(ks * 16 * 2);
            uint32_t af[4][4];
#pragma unroll
            for (int mt = 0; mt < 4; ++mt)
                ldsm_x4(af[mt], aAddr[mt] + kOff);
            uint32_t bf[2][4];
#pragma unroll
            for (int nt2 = 0; nt2 < 2; ++nt2)
                ldsm_x4(bf[nt2], bAddr[nt2] + kOff);
#pragma unroll
            for (int mt = 0; mt < 4; ++mt)
#pragma unroll
                for (int nt = 0; nt < 4; ++nt)
                    mma_f16(acc[mt][nt], af[mt], bf[nt >> 1][nt & 1], bf[nt >> 1][2 + (nt & 1)]);
        }
        sC += STAGE_B; if (sC == NSTAGE * STAGE_B) sC = 0;
    }

#pragma unroll
    for (int mt = 0; mt < 4; ++mt) {
        const int row = m0 + wm * 64 + mt * 16 + qr;
#pragma unroll
        for (int nt = 0; nt < 4; ++nt) {
            const int col = n0 + wn * 32 + nt * 8 + 2 * qc;
            const float2 bv = *(const float2*)&bias[col];
            const float v00 = acc[mt][nt][0] + bv.x, v01 = acc[mt][nt][1] + bv.y;
            const float v10 = acc[mt][nt][2] + bv.x, v11 = acc[mt][nt][3] + bv.y;
            if (HALF_OUT) {
                *(__half2*)&Ch[(size_t)row * N + col]       = __floats2half2_rn(v00, v01);
                *(__half2*)&Ch[(size_t)(row + 8) * N + col] = __floats2half2_rn(v10, v11);
            } else {
                *(float2*)&Cf[(size_t)row * N + col]       = make_float2(v00, v01);
                *(float2*)&Cf[(size_t)(row + 8) * N + col] = make_float2(v10, v11);
            }
        }
    }
}

// ============================================================================
// float -> half bulk convert
// ============================================================================
__global__ void __launch_bounds__(256) f2h_copy(
    const float* __restrict__ src, __half* __restrict__ dst, int n4)
{
    const int i = blockIdx.x * 256 + threadIdx.x;
    if (i < n4) {
        float4 v = ((const float4*)src)[i];
        ((__half2*)dst)[2 * i]     = __floats2half2_rn(v.x, v.y);
        ((__half2*)dst)[2 * i + 1] = __floats2half2_rn(v.z, v.w);
    }
}

// ============================================================================
// Transpose + half convert: dst[Ccols][R] = h(src[R][Ccols])
// ============================================================================
__global__ void __launch_bounds__(256) transpose_h(
    const float* __restrict__ src, __half* __restrict__ dst, int R, int Ccols)
{
    __shared__ float t[32][33];
    const int tx = threadIdx.x & 31;
    const int ty = threadIdx.x >> 5;
    const int c0 = blockIdx.x * 32;
    const int r0 = blockIdx.y * 32;
#pragma unroll
    for (int j = 0; j < 4; ++j)
        t[ty + 8 * j][tx] = src[(size_t)(r0 + ty + 8 * j) * Ccols + c0 + tx];
    __syncthreads();
#pragma unroll
    for (int j = 0; j < 4; ++j)
        dst[(size_t)(c0 + ty + 8 * j) * R + r0 + tx] = __float2half_rn(t[tx][ty + 8 * j]);
}

// ============================================================================
// V transpose per head (half in, half out): g_vh [BH,S,D] -> g_vth [BH,D,S]
// ============================================================================
__global__ void __launch_bounds__(256) transpose_v_h()
{
    __shared__ __half t[32][33];
    const int tx = threadIdx.x & 31;
    const int ty = threadIdx.x >> 5;
    const int d0 = blockIdx.x * 32;
    const int s0 = blockIdx.y * 32;
    const int bh = blockIdx.z;
    const __half* src = g_vh + (size_t)bh * SEQ * HEAD_SIZE;
    __half* dst = g_vth + (size_t)bh * HEAD_SIZE * SEQ;
#pragma unroll
    for (int j = 0; j < 4; ++j)
        t[ty + 8 * j][tx] = src[(size_t)(s0 + ty + 8 * j) * HEAD_SIZE + d0 + tx];
    __syncthreads();
#pragma unroll
    for (int j = 0; j < 4; ++j)
        dst[(size_t)(d0 + ty + 8 * j) * SEQ + s0 + tx] = t[tx][ty + 8 * j];
}

// ============================================================================
// rotary embedding + split (half QKV in): Q (half, pre-scaled) / K / V (half)
// ============================================================================
__global__ void __launch_bounds__(256) rope_split(
    const float* __restrict__ cosb, const float* __restrict__ sinb)
{
    const int t = blockIdx.x;
    const int b = t >> 10;
    const int s = t & 1023;
    const __half* qkv = g_qkvh + (size_t)t * QKV_N;
    const float scale = 0.08838834764831845f;   // 1/sqrt(128)

    for (int idx = threadIdx.x; idx < HIDDEN; idx += blockDim.x) {
        const int h = idx >> 7;
        const int d = idx & 127;
        const size_t src = (size_t)h * HEAD_SIZE + d;
        const size_t dst = ((size_t)(b * NUM_HEADS + h) * SEQ + s) * HEAD_SIZE + d;

        float qv = __half2float(qkv[src]);
        float kv = __half2float(qkv[src + HIDDEN]);
        const __half vv = qkv[src + 2 * HIDDEN];

        if (d < 2 * ROT) {
            if (d < ROT) {
                const float c  = cosb[t * ROT + d];
                const float sn = sinb[t * ROT + d];
                const float q2 = __half2float(qkv[src + ROT]);
                const float k2 = __half2float(qkv[src + HIDDEN + ROT]);
                qv = qv * c - q2 * sn;
                kv = kv * c - k2 * sn;
            } else {
                const int r = d - ROT;
                const float c  = cosb[t * ROT + r];
                const float sn = sinb[t * ROT + r];
                const float q1 = __half2float(qkv[src - ROT]);
                const float k1 = __half2float(qkv[src + HIDDEN - ROT]);
                qv = q1 * sn + qv * c;
                kv = k1 * sn + kv * c;
            }
        }
        g_qh[dst] = __float2half_rn(qv * scale);
        g_kh[dst] = __float2half_rn(kv);
        g_vh[dst] = vv;
    }
}

// ============================================================================
// flash attention v5 — register-resident softmax.
// Block 128 thr = 4 warps; warp w owns score rows w*16..w*16+15 (FULL rows).
// Scores stay in registers; row max/sum via quad shfl; P repacked in-register
// to mma A-fragments. Double-buffered K/Vt tiles, 2 barriers per k-tile.
// ============================================================================
#define FQT 64
#define FKT 64
#define LDK 136    // halves per Q/K row (272B)
#define LDV 72     // halves per Vt row (144B)

struct Flash5Smem {
    __half Qs[FQT][LDK];             // 17408 B
    __half Ks[2][FKT][LDK];          // 34816 B
    __half Vts[2][HEAD_SIZE][LDV];   // 36864 B
};                                    // 89088 B total

__global__ void __launch_bounds__(128) flash_f16_v5()
{
    extern __shared__ char sraw[];
    Flash5Smem& S = *reinterpret_cast<Flash5Smem*>(sraw);

    const int qt = blockIdx.x;
    const int h  = blockIdx.y;
    const int b  = blockIdx.z;
    const int tid  = threadIdx.x;
    const int wid  = tid >> 5;
    const int lane = tid & 31;
    const int qr = lane >> 2;
    const int qc = lane & 3;
    const int lrow = lane & 15;
    const int lcol = (lane >> 4) * 8;
    const int m0 = wid * 16;                 // warp's row band
    const int bh = b * NUM_HEADS + h;
    const size_t headbase = (size_t)bh * SEQ * HEAD_SIZE;
    const size_t vtbase   = (size_t)bh * HEAD_SIZE * SEQ;

    // ---- load Q tile to smem (64x128 halves = 1024 uint4, 8/thread) ----
    {
        const __half* qg = g_qh + headbase + (size_t)(qt * FQT) * HEAD_SIZE;
#pragma unroll
        for (int it = 0; it < 8; ++it) {
            const int flat = it * 128 + tid;
            const int r = flat >> 4;
            const int c = (flat & 15) << 3;
            *(uint4*)&S.Qs[r][c] = *(const uint4*)(qg + (size_t)r * HEAD_SIZE + c);
        }
    }

    // cp.async issue for K/Vt tile kt into buffer buf
    auto issue_tile = [&](int kt, int buf) {
        const __half* kg = g_kh + headbase + (size_t)(kt * FKT) * HEAD_SIZE;
        const uint32_t kd = smem_u32(&S.Ks[buf][0][0]);
#pragma unroll
        for (int it = 0; it < 8; ++it) {
            const int flat = it * 128 + tid;
            const int r = flat >> 4;
            const int c = (flat & 15) << 3;
            asm volatile("cp.async.cg.shared.global [%0], [%1], 16;"
                :: "r"(kd + (uint32_t)(r * LDK + c) * 2u),
                   "l"(kg + (size_t)r * HEAD_SIZE + c) : "memory");
        }
        const __half* vg = g_vth + vtbase + kt * FKT;
        const uint32_t vd = smem_u32(&S.Vts[buf][0][0]);
#pragma unroll
        for (int it = 0; it < 8; ++it) {
            const int flat = it * 128 + tid;
            const int d = flat >> 3;
            const int s8 = (flat & 7) << 3;
            asm volatile("cp.async.cg.shared.global [%0], [%1], 16;"
                :: "r"(vd + (uint32_t)(d * LDV + s8) * 2u),
                   "l"(vg + (size_t)d * SEQ + s8) : "memory");
        }
        asm volatile("cp.async.commit_group;" ::: "memory");
    };

    const int nkt = qt + 1;
    issue_tile(0, 0);
    __syncthreads();   // Q smem stores visible

    // ---- hoist Q fragments into registers (reused across all k-tiles) ----
    uint32_t qf[8][4];
#pragma unroll
    for (int ks = 0; ks < 8; ++ks)
        ldsm_x4(qf[ks], smem_u32(&S.Qs[m0 + lrow][ks * 16 + lcol]));

    // persistent state
    float m0r = -1e30f, m1r = -1e30f, l0r = 0.0f, l1r = 0.0f;
    float oacc[16][4];
#pragma unroll
    for (int i = 0; i < 16; ++i)
#pragma unroll
        for (int j = 0; j < 4; ++j) oacc[i][j] = 0.0f;

    int bufC = 0;
    for (int kt = 0; kt < nkt; ++kt) {
        __syncthreads();   // all warps done reading buf^1 (tile kt-1)
        if (kt + 1 < nkt) {
            issue_tile(kt + 1, bufC ^ 1);
            asm volatile("cp.async.wait_group 1;" ::: "memory");
        } else {
            asm volatile("cp.async.wait_group 0;" ::: "memory");
        }
        __syncthreads();   // tile kt visible to all warps

        // ---- score: S[16x64] per warp, fully in registers ----
        float sacc[8][4];
#pragma unroll
        for (int i = 0; i < 8; ++i)
#pragma unroll
            for (int j = 0; j < 4; ++j) sacc[i][j] = 0.0f;
        {
            const uint32_t kBase = smem_u32(&S.Ks[bufC][lrow][lcol]);
#pragma unroll
            for (int ks = 0; ks < 8; ++ks) {
#pragma unroll
                for (int nt2 = 0; nt2 < 4; ++nt2) {
                    uint32_t bf[4];
                    ldsm_x4(bf, kBase + (uint32_t)(nt2 * 16 * LDK * 2 + ks * 32));
                    mma_f16(sacc[2 * nt2    ], qf[ks], bf[0], bf[2]);
                    mma_f16(sacc[2 * nt2 + 1], qf[ks], bf[1], bf[3]);
                }
            }
        }

        // ---- causal mask (diagonal tile only; local indices) ----
        if (kt == qt) {
            const int lr0 = m0 + qr;       // local row (rows qr, qr+8)
            const int lr1 = m0 + qr + 8;
#pragma unroll
            for (int nt = 0; nt < 8; ++nt) {
                const int lc = nt * 8 + 2 * qc;
                if (lc     > lr0) sacc[nt][0] = -1e30f;
                if (lc + 1 > lr0) sacc[nt][1] = -1e30f;
                if (lc     > lr1) sacc[nt][2] = -1e30f;
                if (lc + 1 > lr1) sacc[nt][3] = -1e30f;
            }
        }

        // ---- in-register online softmax ----
        float mx0 = -1e30f, mx1 = -1e30f;
#pragma unroll
        for (int nt = 0; nt < 8; ++nt) {
            mx0 = fmaxf(mx0, fmaxf(sacc[nt][0], sacc[nt][1]));
            mx1 = fmaxf(mx1, fmaxf(sacc[nt][2], sacc[nt][3]));
        }
        mx0 = fmaxf(mx0, __shfl_xor_sync(0xffffffffu, mx0, 1));
        mx0 = fmaxf(mx0, __shfl_xor_sync(0xffffffffu, mx0, 2));
        mx1 = fmaxf(mx1, __shfl_xor_sync(0xffffffffu, mx1, 1));
        mx1 = fmaxf(mx1, __shfl_xor_sync(0xffffffffu, mx1, 2));

        const float mn0 = fmaxf(m0r, mx0);
        const float mn1 = fmaxf(m1r, mx1);
        const float a0 = __expf(m0r - mn0);
        const float a1 = __expf(m1r - mn1);
        m0r = mn0; m1r = mn1;

        float s0 = 0.0f, s1 = 0.0f;
        uint32_t pf[4][4];    // P as mma A-fragments, built in-register
#pragma unroll
        for (int k2 = 0; k2 < 4; ++k2) {
            const float pa0 = __expf(sacc[2 * k2][0] - mn0);
            const float pa1 = __expf(sacc[2 * k2][1] - mn0);
            const float pb0 = __expf(sacc[2 * k2][2] - mn1);
            const float pb1 = __expf(sacc[2 * k2][3] - mn1);
            const float pc0 = __expf(sacc[2 * k2 + 1][0] - mn0);
            const float pc1 = __expf(sacc[2 * k2 + 1][1] - mn0);
            const float pd0 = __expf(sacc[2 * k2 + 1][2] - mn1);
            const float pd1 = __expf(sacc[2 * k2 + 1][3] - mn1);
            s0 += pa0 + pa1 + pc0 + pc1;
            s1 += pb0 + pb1 + pd0 + pd1;
            pf[k2][0] = pack_h2(pa0, pa1);   // row qr,   k = k2*16 + 2qc..
            pf[k2][1] = pack_h2(pb0, pb1);   // row qr+8, k = k2*16 + 2qc..
            pf[k2][2] = pack_h2(pc0, pc1);   // row qr,   k = k2*16 + 8 + 2qc..
            pf[k2][3] = pack_h2(pd0, pd1);   // row qr+8, k = k2*16 + 8 + 2qc..
        }
        s0 += __shfl_xor_sync(0xffffffffu, s0, 1);
        s0 += __shfl_xor_sync(0xffffffffu, s0, 2);
        s1 += __shfl_xor_sync(0xffffffffu, s1, 1);
        s1 += __shfl_xor_sync(0xffffffffu, s1, 2);
        l0r = l0r * a0 + s0;
        l1r = l1r * a1 + s1;

        // ---- rescale O, then PV: O[16x128] += P[16x64] @ V ----
#pragma unroll
        for (int nt = 0; nt < 16; ++nt) {
            oacc[nt][0] *= a0; oacc[nt][1] *= a0;
            oacc[nt][2] *= a1; oacc[nt][3] *= a1;
        }
        {
            const uint32_t vBase = smem_u32(&S.Vts[bufC][lrow][lcol]);
#pragma unroll
            for (int k2 = 0; k2 < 4; ++k2) {
#pragma unroll
                for (int nt2 = 0; nt2 < 8; ++nt2) {
                    uint32_t bf[4];
                    ldsm_x4(bf, vBase + (uint32_t)(nt2 * 16 * LDV * 2 + k2 * 32));
                    mma_f16(oacc[2 * nt2    ], pf[k2], bf[0], bf[2]);
                    mma_f16(oacc[2 * nt2 + 1], pf[k2], bf[1], bf[3]);
                }
            }
        }
        bufC ^= 1;
    }

    // ---- epilogue: normalize, write half ----
    {
        const int t0 = b * SEQ + qt * FQT;
        const float inv0 = 1.0f / l0r;
        const float inv1 = 1.0f / l1r;
        const int row0 = t0 + m0 + qr;
#pragma unroll
        for (int nt = 0; nt < 16; ++nt) {
            const int col = h * HEAD_SIZE + nt * 8 + 2 * qc;
            *(__half2*)&g_attnh[(size_t)row0 * HIDDEN + col] =
                __floats2half2_rn(oacc[nt][0] * inv0, oacc[nt][1] * inv0);
            *(__half2*)&g_attnh[(size_t)(row0 + 8) * HIDDEN + col] =
                __floats2half2_rn(oacc[nt][2] * inv1, oacc[nt][3] * inv1);
        }
    }
}

// ============================================================================
// launch
// ============================================================================
extern "C" void kernel_launch(void* const* d_in, const int* in_sizes, int n_in,
                              void* d_out, int out_size)
{
    const float* hidden  = (const float*)d_in[0];
    const float* cosb    = (const float*)d_in[1];
    const float* sinb    = (const float*)d_in[2];
    const float* W_qkv   = (const float*)d_in[3];
    const float* b_qkv   = (const float*)d_in[4];
    const float* W_dense = (const float*)d_in[5];
    const float* b_dense = (const float*)d_in[6];
    float* out = (float*)d_out;

    __half *qkvh_ptr, *attnh_ptr, *hidh_ptr, *wqkvTh_ptr, *wdenseTh_ptr;
    cudaGetSymbolAddress((void**)&qkvh_ptr, g_qkvh);
    cudaGetSymbolAddress((void**)&attnh_ptr, g_attnh);
    cudaGetSymbolAddress((void**)&hidh_ptr, g_hidh);
    cudaGetSymbolAddress((void**)&wqkvTh_ptr, g_wqkvTh);
    cudaGetSymbolAddress((void**)&wdenseTh_ptr, g_wdenseTh);

    cudaFuncSetAttribute(flash_f16_v5, cudaFuncAttributeMaxDynamicSharedMemorySize,
                         (int)sizeof(Flash5Smem));
    cudaFuncSetAttribute(gemm_f16_v3<true>,  cudaFuncAttributeMaxDynamicSharedMemorySize,
                         GEMM_SMEM_BYTES);
    cudaFuncSetAttribute(gemm_f16_v3<false>, cudaFuncAttributeMaxDynamicSharedMemorySize,
                         GEMM_SMEM_BYTES);

    // 0) operand prep (half)
    {
        const int n4 = TOTAL * HIDDEN / 4;
        f2h_copy<<<(n4 + 255) / 256, 256>>>(hidden, hidh_ptr, n4);
        transpose_h<<<dim3(QKV_N / 32, HIDDEN / 32), 256>>>(W_qkv, wqkvTh_ptr, HIDDEN, QKV_N);
        transpose_h<<<dim3(HIDDEN / 32, HIDDEN / 32), 256>>>(W_dense, wdenseTh_ptr, HIDDEN, HIDDEN);
    }
    // 1) QKV projection (fp16 mma v3, half output)
    gemm_f16_v3<true><<<dim3(QKV_N / 128, TOTAL / 128), 256, GEMM_SMEM_BYTES>>>(
        hidh_ptr, wqkvTh_ptr, b_qkv, nullptr, qkvh_ptr, TOTAL, QKV_N, HIDDEN);
    // 2) rotary + split (all half)
    rope_split<<<TOTAL, 256>>>(cosb, sinb);
    // 2b) V transpose per head (half->half)
    transpose_v_h<<<dim3(HEAD_SIZE / 32, SEQ / 32, BATCH * NUM_HEADS), 256>>>();
    // 3) causal flash attention v5 (register softmax)
    flash_f16_v5<<<dim3(SEQ / FQT, NUM_HEADS, BATCH), 128, sizeof(Flash5Smem)>>>();
    // 4) dense projection (fp16 mma v3, fp32 output)
    gemm_f16_v3<false><<<dim3(HIDDEN / 128, TOTAL / 128), 256, GEMM_SMEM_BYTES>>>(
        attnh_ptr, wdenseTh_ptr, b_dense, out, nullptr, TOTAL, HIDDEN, HIDDEN);
}

// round 12
// speedup vs baseline: 1.1246x; 1.0523x over previous
#include <cuda_runtime.h>
#include <cuda.h>
#include <cuda_fp16.h>
#include <math.h>
#include <stdint.h>

// Problem constants
#define NUM_HEADS 16
#define HEAD_SIZE 128
#define HIDDEN    2048
#define ROT       16
#define BATCH     4
#define SEQ       1024
#define TOTAL     4096
#define QKV_N     6144

// -------- device scratch --------
__device__ __half g_qh[(size_t)TOTAL * HIDDEN];        // Q half, pre-scaled, [B,H,S,D]
__device__ __half g_kh[(size_t)TOTAL * HIDDEN];        // K half, [B,H,S,D]
__device__ __half g_vh[(size_t)TOTAL * HIDDEN];        // V half, [B,H,S,D]
__device__ __half g_vth[(size_t)BATCH * NUM_HEADS * HEAD_SIZE * SEQ];  // V^T half [B,H,D,S]
__device__ __half g_attnh[(size_t)TOTAL * HIDDEN];     // flash output (half)
__device__ __half g_hidh[(size_t)TOTAL * HIDDEN];      // hidden states (half)
__device__ __half g_wqkvTh[(size_t)QKV_N * HIDDEN];    // W_qkv^T [N][K] half
__device__ __half g_wdenseTh[(size_t)HIDDEN * HIDDEN]; // W_dense^T [N][K] half

// ============================================================================
// helpers
// ============================================================================
__device__ __forceinline__ uint32_t smem_u32(const void* p) {
    uint32_t a;
    asm("{ .reg .u64 t; cvta.to.shared.u64 t, %1; cvt.u32.u64 %0, t; }" : "=r"(a) : "l"(p));
    return a;
}
__device__ __forceinline__ void mma_f16(float* c, const uint32_t* a, uint32_t b0, uint32_t b1) {
    asm volatile(
        "mma.sync.aligned.m16n8k16.row.col.f32.f16.f16.f32 "
        "{%0,%1,%2,%3}, {%4,%5,%6,%7}, {%8,%9}, {%0,%1,%2,%3};"
        : "+f"(c[0]), "+f"(c[1]), "+f"(c[2]), "+f"(c[3])
        : "r"(a[0]), "r"(a[1]), "r"(a[2]), "r"(a[3]), "r"(b0), "r"(b1));
}
__device__ __forceinline__ void ldsm_x4(uint32_t* r, uint32_t addr) {
    asm volatile("ldmatrix.sync.aligned.m8n8.x4.shared.b16 {%0,%1,%2,%3}, [%4];"
        : "=r"(r[0]), "=r"(r[1]), "=r"(r[2]), "=r"(r[3]) : "r"(addr));
}
__device__ __forceinline__ uint32_t pack_h2(float a, float b) {
    __half2 h = __floats2half2_rn(a, b);
    return *(uint32_t*)&h;
}

// ============================================================================
// GEMM common config (mainloop identical to the round-9 validated v3)
// ============================================================================
#define NSTAGE 3
#define KCH 64
#define LDH 72
#define GEMM_STAGE (128 * LDH)
#define STAGE_B (GEMM_STAGE * 2)
#define GEMM_SMEM_BYTES (NSTAGE * STAGE_B * 2)   // 110592 B

// Mainloop macro: computes acc[4][4][4] for the 128x128 tile at (m0, n0).
#define GEMM_MAINLOOP(Aptr, Bptr, Kdim)                                          \
    extern __shared__ __half hsm[];                                             \
    __half* As = hsm;                                                           \
    __half* Bs = hsm + NSTAGE * GEMM_STAGE;                                     \
    const int tid  = threadIdx.x;                                               \
    const int wid  = tid >> 5;                                                  \
    const int lane = tid & 31;                                                  \
    const int wm = wid >> 2;                                                    \
    const int wn = wid & 3;                                                     \
    const int qr = lane >> 2;                                                   \
    const int qc = lane & 3;                                                    \
    const int m0 = blockIdx.y * 128;                                            \
    const int n0 = blockIdx.x * 128;                                            \
    const int lrow = lane & 15;                                                 \
    const int lcol = (lane >> 4) * 8;                                           \
    const int row0 = tid >> 3;                                                  \
    const int c8   = (tid & 7) << 3;                                            \
    const __half* srcA = (Aptr) + (size_t)(m0 + row0) * (Kdim) + c8;            \
    const __half* srcB = (Bptr) + (size_t)(n0 + row0) * (Kdim) + c8;            \
    const uint32_t dA0 = smem_u32(As) + (uint32_t)(row0 * LDH + c8) * 2u;       \
    const uint32_t dB0 = smem_u32(Bs) + (uint32_t)(row0 * LDH + c8) * 2u;       \
    const size_t gRow = (size_t)32 * (Kdim);                                    \
    const uint32_t sRow = 32u * LDH * 2u;                                       \
    uint32_t aAddr[4], bAddr[2];                                                \
    _Pragma("unroll")                                                           \
    for (int mt = 0; mt < 4; ++mt)                                              \
        aAddr[mt] = smem_u32(As) + (uint32_t)((wm * 64 + mt * 16 + lrow) * LDH + lcol) * 2u; \
    _Pragma("unroll")                                                           \
    for (int nt2 = 0; nt2 < 2; ++nt2)                                           \
        bAddr[nt2] = smem_u32(Bs) + (uint32_t)((wn * 32 + nt2 * 16 + lrow) * LDH + lcol) * 2u; \
    float acc[4][4][4];                                                         \
    _Pragma("unroll")                                                           \
    for (int i = 0; i < 4; ++i)                                                 \
        _Pragma("unroll")                                                       \
        for (int j = 0; j < 4; ++j)                                             \
            _Pragma("unroll")                                                   \
            for (int k = 0; k < 4; ++k) acc[i][j][k] = 0.0f;                    \
    auto load_chunk = [&](const __half* pA, const __half* pB, uint32_t sOff) {  \
        _Pragma("unroll")                                                       \
        for (int it = 0; it < 4; ++it) {                                        \
            asm volatile("cp.async.cg.shared.global [%0], [%1], 16;"            \
                :: "r"(dA0 + sOff + it * sRow), "l"(pA + it * gRow) : "memory");\
            asm volatile("cp.async.cg.shared.global [%0], [%1], 16;"            \
                :: "r"(dB0 + sOff + it * sRow), "l"(pB + it * gRow) : "memory");\
        }                                                                       \
        asm volatile("cp.async.commit_group;" ::: "memory");                    \
    };                                                                          \
    const int NCH = (Kdim) / KCH;                                               \
    load_chunk(srcA, srcB, 0);                                                  \
    srcA += KCH; srcB += KCH;                                                   \
    load_chunk(srcA, srcB, STAGE_B);                                            \
    srcA += KCH; srcB += KCH;                                                   \
    uint32_t sC = 0;                                                            \
    uint32_t sL = 2 * STAGE_B;                                                  \
    for (int c = 0; c < NCH; ++c) {                                             \
        if (c + 1 < NCH) { asm volatile("cp.async.wait_group 1;" ::: "memory"); }\
        else             { asm volatile("cp.async.wait_group 0;" ::: "memory"); }\
        __syncthreads();                                                        \
        if (c + 2 < NCH) {                                                      \
            load_chunk(srcA, srcB, sL);                                         \
            srcA += KCH; srcB += KCH;                                           \
            sL += STAGE_B; if (sL == NSTAGE * STAGE_B) sL = 0;                  \
        }                                                                       \
        _Pragma("unroll")                                                       \
        for (int ks = 0; ks < 4; ++ks) {                                        \
            const uint32_t kOff = sC + (uint32_t)(ks * 16 * 2);                 \
            uint32_t af[4][4];                                                  \
            _Pragma("unroll")                                                   \
            for (int mt = 0; mt < 4; ++mt)                                      \
                ldsm_x4(af[mt], aAddr[mt] + kOff);                              \
            uint32_t bf[2][4];                                                  \
            _Pragma("unroll")                                                   \
            for (int nt2 = 0; nt2 < 2; ++nt2)                                   \
                ldsm_x4(bf[nt2], bAddr[nt2] + kOff);                            \
            _Pragma("unroll")                                                   \
            for (int mt = 0; mt < 4; ++mt)                                      \
                _Pragma("unroll")                                               \
                for (int nt = 0; nt < 4; ++nt)                                  \
                    mma_f16(acc[mt][nt], af[mt], bf[nt >> 1][nt & 1], bf[nt >> 1][2 + (nt & 1)]); \
        }                                                                       \
        sC += STAGE_B; if (sC == NSTAGE * STAGE_B) sC = 0;                      \
    }

// ============================================================================
// Kernel A: QKV GEMM with FUSED bias + RoPE + split epilogue.
// Writes g_qh (pre-scaled half), g_kh, g_vh directly in [B,H,S,D].
// ============================================================================
__global__ void __launch_bounds__(256, 2) gemm_qkv_rope(
    const __half* __restrict__ A, const __half* __restrict__ Bt,
    const float* __restrict__ bias,
    const float* __restrict__ cosb, const float* __restrict__ sinb)
{
    GEMM_MAINLOOP(A, Bt, HIDDEN)

    // ---- fused epilogue ----
    const int col0 = n0 + wn * 32;             // 32-aligned; no head/qkv straddle
    const int which = col0 >> 11;              // 0=q, 1=k, 2=v
    const int hd = (col0 & 2047) >> 7;         // head
    const int d0 = col0 & 127;                 // dim base within head
    __half* outBase = (which == 0) ? g_qh : (which == 1) ? g_kh : g_vh;
    const bool ropez = (d0 == 0) && (which < 2);
    const float qs = (which == 0) ? 0.08838834764831845f : 1.0f;

#pragma unroll
    for (int mt = 0; mt < 4; ++mt) {
        const int t0 = m0 + wm * 64 + mt * 16 + qr;   // token rows t0, t0+8
        const int t1 = t0 + 8;

        float vals[4][4];
#pragma unroll
        for (int nt = 0; nt < 4; ++nt) {
            const int col = col0 + nt * 8 + 2 * qc;
            const float2 bv = *(const float2*)&bias[col];
            vals[nt][0] = acc[mt][nt][0] + bv.x;
            vals[nt][1] = acc[mt][nt][1] + bv.y;
            vals[nt][2] = acc[mt][nt][2] + bv.x;
            vals[nt][3] = acc[mt][nt][3] + bv.y;
        }

        if (ropez) {
            // d = nt*8 + 2qc (< 16) pairs with d+16 = (nt+2)*8 + 2qc
#pragma unroll
            for (int nt = 0; nt < 2; ++nt) {
                const int r = nt * 8 + 2 * qc;     // even, 0..14
                const float c0a = cosb[t0 * ROT + r],     s0a = sinb[t0 * ROT + r];
                const float c0b = cosb[t0 * ROT + r + 1], s0b = sinb[t0 * ROT + r + 1];
                const float c1a = cosb[t1 * ROT + r],     s1a = sinb[t1 * ROT + r];
                const float c1b = cosb[t1 * ROT + r + 1], s1b = sinb[t1 * ROT + r + 1];
                float x1, x2;
                x1 = vals[nt][0]; x2 = vals[nt + 2][0];
                vals[nt][0] = x1 * c0a - x2 * s0a; vals[nt + 2][0] = x1 * s0a + x2 * c0a;
                x1 = vals[nt][1]; x2 = vals[nt + 2][1];
                vals[nt][1] = x1 * c0b - x2 * s0b; vals[nt + 2][1] = x1 * s0b + x2 * c0b;
                x1 = vals[nt][2]; x2 = vals[nt + 2][2];
                vals[nt][2] = x1 * c1a - x2 * s1a; vals[nt + 2][2] = x1 * s1a + x2 * c1a;
                x1 = vals[nt][3]; x2 = vals[nt + 2][3];
                vals[nt][3] = x1 * c1b - x2 * s1b; vals[nt + 2][3] = x1 * s1b + x2 * c1b;
            }
        }

        const int b0i = t0 >> 10, s0i = t0 & 1023;
        const int b1i = t1 >> 10, s1i = t1 & 1023;
        const size_t base0 = ((size_t)(b0i * NUM_HEADS + hd) * SEQ + s0i) * HEAD_SIZE;
        const size_t base1 = ((size_t)(b1i * NUM_HEADS + hd) * SEQ + s1i) * HEAD_SIZE;
#pragma unroll
        for (int nt = 0; nt < 4; ++nt) {
            const int d = d0 + nt * 8 + 2 * qc;
            *(__half2*)&outBase[base0 + d] =
                __floats2half2_rn(vals[nt][0] * qs, vals[nt][1] * qs);
            *(__half2*)&outBase[base1 + d] =
                __floats2half2_rn(vals[nt][2] * qs, vals[nt][3] * qs);
        }
    }
}

// ============================================================================
// Kernel B: dense GEMM (fp32 output + bias) — unchanged v3 behavior
// ============================================================================
__global__ void __launch_bounds__(256, 2) gemm_dense(
    const __half* __restrict__ A, const __half* __restrict__ Bt,
    const float* __restrict__ bias, float* __restrict__ Cf)
{
    GEMM_MAINLOOP(A, Bt, HIDDEN)

#pragma unroll
    for (int mt = 0; mt < 4; ++mt) {
        const int row = m0 + wm * 64 + mt * 16 + qr;
#pragma unroll
        for (int nt = 0; nt < 4; ++nt) {
            const int col = n0 + wn * 32 + nt * 8 + 2 * qc;
            const float2 bv = *(const float2*)&bias[col];
            *(float2*)&Cf[(size_t)row * HIDDEN + col] =
                make_float2(acc[mt][nt][0] + bv.x, acc[mt][nt][1] + bv.y);
            *(float2*)&Cf[(size_t)(row + 8) * HIDDEN + col] =
                make_float2(acc[mt][nt][2] + bv.x, acc[mt][nt][3] + bv.y);
        }
    }
}

// ============================================================================
// float -> half bulk convert
// ============================================================================
__global__ void __launch_bounds__(256) f2h_copy(
    const float* __restrict__ src, __half* __restrict__ dst, int n4)
{
    const int i = blockIdx.x * 256 + threadIdx.x;
    if (i < n4) {
        float4 v = ((const float4*)src)[i];
        ((__half2*)dst)[2 * i]     = __floats2half2_rn(v.x, v.y);
        ((__half2*)dst)[2 * i + 1] = __floats2half2_rn(v.z, v.w);
    }
}

// ============================================================================
// Transpose + half convert: dst[Ccols][R] = h(src[R][Ccols])
// ============================================================================
__global__ void __launch_bounds__(256) transpose_h(
    const float* __restrict__ src, __half* __restrict__ dst, int R, int Ccols)
{
    __shared__ float t[32][33];
    const int tx = threadIdx.x & 31;
    const int ty = threadIdx.x >> 5;
    const int c0 = blockIdx.x * 32;
    const int r0 = blockIdx.y * 32;
#pragma unroll
    for (int j = 0; j < 4; ++j)
        t[ty + 8 * j][tx] = src[(size_t)(r0 + ty + 8 * j) * Ccols + c0 + tx];
    __syncthreads();
#pragma unroll
    for (int j = 0; j < 4; ++j)
        dst[(size_t)(c0 + ty + 8 * j) * R + r0 + tx] = __float2half_rn(t[tx][ty + 8 * j]);
}

// ============================================================================
// V transpose per head (half in, half out): g_vh [BH,S,D] -> g_vth [BH,D,S]
// ============================================================================
__global__ void __launch_bounds__(256) transpose_v_h()
{
    __shared__ __half t[32][33];
    const int tx = threadIdx.x & 31;
    const int ty = threadIdx.x >> 5;
    const int d0 = blockIdx.x * 32;
    const int s0 = blockIdx.y * 32;
    const int bh = blockIdx.z;
    const __half* src = g_vh + (size_t)bh * SEQ * HEAD_SIZE;
    __half* dst = g_vth + (size_t)bh * HEAD_SIZE * SEQ;
#pragma unroll
    for (int j = 0; j < 4; ++j)
        t[ty + 8 * j][tx] = src[(size_t)(s0 + ty + 8 * j) * HEAD_SIZE + d0 + tx];
    __syncthreads();
#pragma unroll
    for (int j = 0; j < 4; ++j)
        dst[(size_t)(d0 + ty + 8 * j) * SEQ + s0 + tx] = t[tx][ty + 8 * j];
}

// ============================================================================
// flash attention v5 — register-resident softmax (unchanged from round 11)
// ============================================================================
#define FQT 64
#define FKT 64
#define LDK 136
#define LDV 72

struct Flash5Smem {
    __half Qs[FQT][LDK];
    __half Ks[2][FKT][LDK];
    __half Vts[2][HEAD_SIZE][LDV];
};

__global__ void __launch_bounds__(128) flash_f16_v5()
{
    extern __shared__ char sraw[];
    Flash5Smem& S = *reinterpret_cast<Flash5Smem*>(sraw);

    const int qt = blockIdx.x;
    const int h  = blockIdx.y;
    const int b  = blockIdx.z;
    const int tid  = threadIdx.x;
    const int wid  = tid >> 5;
    const int lane = tid & 31;
    const int qr = lane >> 2;
    const int qc = lane & 3;
    const int lrow = lane & 15;
    const int lcol = (lane >> 4) * 8;
    const int m0 = wid * 16;
    const int bh = b * NUM_HEADS + h;
    const size_t headbase = (size_t)bh * SEQ * HEAD_SIZE;
    const size_t vtbase   = (size_t)bh * HEAD_SIZE * SEQ;

    {
        const __half* qg = g_qh + headbase + (size_t)(qt * FQT) * HEAD_SIZE;
#pragma unroll
        for (int it = 0; it < 8; ++it) {
            const int flat = it * 128 + tid;
            const int r = flat >> 4;
            const int c = (flat & 15) << 3;
            *(uint4*)&S.Qs[r][c] = *(const uint4*)(qg + (size_t)r * HEAD_SIZE + c);
        }
    }

    auto issue_tile = [&](int kt, int buf) {
        const __half* kg = g_kh + headbase + (size_t)(kt * FKT) * HEAD_SIZE;
        const uint32_t kd = smem_u32(&S.Ks[buf][0][0]);
#pragma unroll
        for (int it = 0; it < 8; ++it) {
            const int flat = it * 128 + tid;
            const int r = flat >> 4;
            const int c = (flat & 15) << 3;
            asm volatile("cp.async.cg.shared.global [%0], [%1], 16;"
                :: "r"(kd + (uint32_t)(r * LDK + c) * 2u),
                   "l"(kg + (size_t)r * HEAD_SIZE + c) : "memory");
        }
        const __half* vg = g_vth + vtbase + kt * FKT;
        const uint32_t vd = smem_u32(&S.Vts[buf][0][0]);
#pragma unroll
        for (int it = 0; it < 8; ++it) {
            const int flat = it * 128 + tid;
            const int d = flat >> 3;
            const int s8 = (flat & 7) << 3;
            asm volatile("cp.async.cg.shared.global [%0], [%1], 16;"
                :: "r"(vd + (uint32_t)(d * LDV + s8) * 2u),
                   "l"(vg + (size_t)d * SEQ + s8) : "memory");
        }
        asm volatile("cp.async.commit_group;" ::: "memory");
    };

    const int nkt = qt + 1;
    issue_tile(0, 0);
    __syncthreads();

    uint32_t qf[8][4];
#pragma unroll
    for (int ks = 0; ks < 8; ++ks)
        ldsm_x4(qf[ks], smem_u32(&S.Qs[m0 + lrow][ks * 16 + lcol]));

    float m0r = -1e30f, m1r = -1e30f, l0r = 0.0f, l1r = 0.0f;
    float oacc[16][4];
#pragma unroll
    for (int i = 0; i < 16; ++i)
#pragma unroll
        for (int j = 0; j < 4; ++j) oacc[i][j] = 0.0f;

    int bufC = 0;
    for (int kt = 0; kt < nkt; ++kt) {
        __syncthreads();
        if (kt + 1 < nkt) {
            issue_tile(kt + 1, bufC ^ 1);
            asm volatile("cp.async.wait_group 1;" ::: "memory");
        } else {
            asm volatile("cp.async.wait_group 0;" ::: "memory");
        }
        __syncthreads();

        float sacc[8][4];
#pragma unroll
        for (int i = 0; i < 8; ++i)
#pragma unroll
            for (int j = 0; j < 4; ++j) sacc[i][j] = 0.0f;
        {
            const uint32_t kBase = smem_u32(&S.Ks[bufC][lrow][lcol]);
#pragma unroll
            for (int ks = 0; ks < 8; ++ks) {
#pragma unroll
                for (int nt2 = 0; nt2 < 4; ++nt2) {
                    uint32_t bf[4];
                    ldsm_x4(bf, kBase + (uint32_t)(nt2 * 16 * LDK * 2 + ks * 32));
                    mma_f16(sacc[2 * nt2    ], qf[ks], bf[0], bf[2]);
                    mma_f16(sacc[2 * nt2 + 1], qf[ks], bf[1], bf[3]);
                }
            }
        }

        if (kt == qt) {
            const int lr0 = m0 + qr;
            const int lr1 = m0 + qr + 8;
#pragma unroll
            for (int nt = 0; nt < 8; ++nt) {
                const int lc = nt * 8 + 2 * qc;
                if (lc     > lr0) sacc[nt][0] = -1e30f;
                if (lc + 1 > lr0) sacc[nt][1] = -1e30f;
                if (lc     > lr1) sacc[nt][2] = -1e30f;
                if (lc + 1 > lr1) sacc[nt][3] = -1e30f;
            }
        }

        float mx0 = -1e30f, mx1 = -1e30f;
#pragma unroll
        for (int nt = 0; nt < 8; ++nt) {
            mx0 = fmaxf(mx0, fmaxf(sacc[nt][0], sacc[nt][1]));
            mx1 = fmaxf(mx1, fmaxf(sacc[nt][2], sacc[nt][3]));
        }
        mx0 = fmaxf(mx0, __shfl_xor_sync(0xffffffffu, mx0, 1));
        mx0 = fmaxf(mx0, __shfl_xor_sync(0xffffffffu, mx0, 2));
        mx1 = fmaxf(mx1, __shfl_xor_sync(0xffffffffu, mx1, 1));
        mx1 = fmaxf(mx1, __shfl_xor_sync(0xffffffffu, mx1, 2));

        const float mn0 = fmaxf(m0r, mx0);
        const float mn1 = fmaxf(m1r, mx1);
        const float a0 = __expf(m0r - mn0);
        const float a1 = __expf(m1r - mn1);
        m0r = mn0; m1r = mn1;

        float s0 = 0.0f, s1 = 0.0f;
        uint32_t pf[4][4];
#pragma unroll
        for (int k2 = 0; k2 < 4; ++k2) {
            const float pa0 = __expf(sacc[2 * k2][0] - mn0);
            const float pa1 = __expf(sacc[2 * k2][1] - mn0);
            const float pb0 = __expf(sacc[2 * k2][2] - mn1);
            const float pb1 = __expf(sacc[2 * k2][3] - mn1);
            const float pc0 = __expf(sacc[2 * k2 + 1][0] - mn0);
            const float pc1 = __expf(sacc[2 * k2 + 1][1] - mn0);
            const float pd0 = __expf(sacc[2 * k2 + 1][2] - mn1);
            const float pd1 = __expf(sacc[2 * k2 + 1][3] - mn1);
            s0 += pa0 + pa1 + pc0 + pc1;
            s1 += pb0 + pb1 + pd0 + pd1;
            pf[k2][0] = pack_h2(pa0, pa1);
            pf[k2][1] = pack_h2(pb0, pb1);
            pf[k2][2] = pack_h2(pc0, pc1);
            pf[k2][3] = pack_h2(pd0, pd1);
        }
        s0 += __shfl_xor_sync(0xffffffffu, s0, 1);
        s0 += __shfl_xor_sync(0xffffffffu, s0, 2);
        s1 += __shfl_xor_sync(0xffffffffu, s1, 1);
        s1 += __shfl_xor_sync(0xffffffffu, s1, 2);
        l0r = l0r * a0 + s0;
        l1r = l1r * a1 + s1;

#pragma unroll
        for (int nt = 0; nt < 16; ++nt) {
            oacc[nt][0] *= a0; oacc[nt][1] *= a0;
            oacc[nt][2] *= a1; oacc[nt][3] *= a1;
        }
        {
            const uint32_t vBase = smem_u32(&S.Vts[bufC][lrow][lcol]);
#pragma unroll
            for (int k2 = 0; k2 < 4; ++k2) {
#pragma unroll
                for (int nt2 = 0; nt2 < 8; ++nt2) {
                    uint32_t bf[4];
                    ldsm_x4(bf, vBase + (uint32_t)(nt2 * 16 * LDV * 2 + k2 * 32));
                    mma_f16(oacc[2 * nt2    ], pf[k2], bf[0], bf[2]);
                    mma_f16(oacc[2 * nt2 + 1], pf[k2], bf[1], bf[3]);
                }
            }
        }
        bufC ^= 1;
    }

    {
        const int t0 = b * SEQ + qt * FQT;
        const float inv0 = 1.0f / l0r;
        const float inv1 = 1.0f / l1r;
        const int row0 = t0 + m0 + qr;
#pragma unroll
        for (int nt = 0; nt < 16; ++nt) {
            const int col = h * HEAD_SIZE + nt * 8 + 2 * qc;
            *(__half2*)&g_attnh[(size_t)row0 * HIDDEN + col] =
                __floats2half2_rn(oacc[nt][0] * inv0, oacc[nt][1] * inv0);
            *(__half2*)&g_attnh[(size_t)(row0 + 8) * HIDDEN + col] =
                __floats2half2_rn(oacc[nt][2] * inv1, oacc[nt][3] * inv1);
        }
    }
}

// ============================================================================
// launch
// ============================================================================
extern "C" void kernel_launch(void* const* d_in, const int* in_sizes, int n_in,
                              void* d_out, int out_size)
{
    const float* hidden  = (const float*)d_in[0];
    const float* cosb    = (const float*)d_in[1];
    const float* sinb    = (const float*)d_in[2];
    const float* W_qkv   = (const float*)d_in[3];
    const float* b_qkv   = (const float*)d_in[4];
    const float* W_dense = (const float*)d_in[5];
    const float* b_dense = (const float*)d_in[6];
    float* out = (float*)d_out;

    __half *attnh_ptr, *hidh_ptr, *wqkvTh_ptr, *wdenseTh_ptr;
    cudaGetSymbolAddress((void**)&attnh_ptr, g_attnh);
    cudaGetSymbolAddress((void**)&hidh_ptr, g_hidh);
    cudaGetSymbolAddress((void**)&wqkvTh_ptr, g_wqkvTh);
    cudaGetSymbolAddress((void**)&wdenseTh_ptr, g_wdenseTh);

    cudaFuncSetAttribute(flash_f16_v5, cudaFuncAttributeMaxDynamicSharedMemorySize,
                         (int)sizeof(Flash5Smem));
    cudaFuncSetAttribute(gemm_qkv_rope, cudaFuncAttributeMaxDynamicSharedMemorySize,
                         GEMM_SMEM_BYTES);
    cudaFuncSetAttribute(gemm_dense, cudaFuncAttributeMaxDynamicSharedMemorySize,
                         GEMM_SMEM_BYTES);

    // 0) operand prep (half)
    {
        const int n4 = TOTAL * HIDDEN / 4;
        f2h_copy<<<(n4 + 255) / 256, 256>>>(hidden, hidh_ptr, n4);
        transpose_h<<<dim3(QKV_N / 32, HIDDEN / 32), 256>>>(W_qkv, wqkvTh_ptr, HIDDEN, QKV_N);
        transpose_h<<<dim3(HIDDEN / 32, HIDDEN / 32), 256>>>(W_dense, wdenseTh_ptr, HIDDEN, HIDDEN);
    }
    // 1) QKV projection with fused bias+RoPE+split epilogue
    gemm_qkv_rope<<<dim3(QKV_N / 128, TOTAL / 128), 256, GEMM_SMEM_BYTES>>>(
        hidh_ptr, wqkvTh_ptr, b_qkv, cosb, sinb);
    // 2) V transpose per head (half->half)
    transpose_v_h<<<dim3(HEAD_SIZE / 32, SEQ / 32, BATCH * NUM_HEADS), 256>>>();
    // 3) causal flash attention v5 (register softmax)
    flash_f16_v5<<<dim3(SEQ / FQT, NUM_HEADS, BATCH), 128, sizeof(Flash5Smem)>>>();
    // 4) dense projection (fp32 output)
    gemm_dense<<<dim3(HIDDEN / 128, TOTAL / 128), 256, GEMM_SMEM_BYTES>>>(
        attnh_ptr, wdenseTh_ptr, b_dense, out);
}

// round 13
// speedup vs baseline: 1.2815x; 1.1395x over previous
#include <cuda_runtime.h>
#include <cuda.h>
#include <cuda_fp16.h>
#include <math.h>
#include <stdint.h>

// Problem constants
#define NUM_HEADS 16
#define HEAD_SIZE 128
#define HIDDEN    2048
#define ROT       16
#define BATCH     4
#define SEQ       1024
#define TOTAL     4096
#define QKV_N     6144

// -------- device scratch --------
__device__ __half g_qh[(size_t)TOTAL * HIDDEN];        // Q half, pre-scaled, [B,H,S,D]
__device__ __half g_kh[(size_t)TOTAL * HIDDEN];        // K half, [B,H,S,D]
__device__ __half g_vh[(size_t)TOTAL * HIDDEN];        // V half, [B,H,S,D]
__device__ __half g_attnh[(size_t)TOTAL * HIDDEN];     // flash output (half)
__device__ __half g_hidh[(size_t)TOTAL * HIDDEN];      // hidden states (half)
__device__ __half g_wqkvh[(size_t)HIDDEN * QKV_N];     // W_qkv [K][N] half (orig layout)
__device__ __half g_wdenseh[(size_t)HIDDEN * HIDDEN];  // W_dense [K][N] half

// ============================================================================
// helpers
// ============================================================================
__device__ __forceinline__ uint32_t smem_u32(const void* p) {
    uint32_t a;
    asm("{ .reg .u64 t; cvta.to.shared.u64 t, %1; cvt.u32.u64 %0, t; }" : "=r"(a) : "l"(p));
    return a;
}
__device__ __forceinline__ void mma_f16(float* c, const uint32_t* a, uint32_t b0, uint32_t b1) {
    asm volatile(
        "mma.sync.aligned.m16n8k16.row.col.f32.f16.f16.f32 "
        "{%0,%1,%2,%3}, {%4,%5,%6,%7}, {%8,%9}, {%0,%1,%2,%3};"
        : "+f"(c[0]), "+f"(c[1]), "+f"(c[2]), "+f"(c[3])
        : "r"(a[0]), "r"(a[1]), "r"(a[2]), "r"(a[3]), "r"(b0), "r"(b1));
}
__device__ __forceinline__ void ldsm_x4(uint32_t* r, uint32_t addr) {
    asm volatile("ldmatrix.sync.aligned.m8n8.x4.shared.b16 {%0,%1,%2,%3}, [%4];"
        : "=r"(r[0]), "=r"(r[1]), "=r"(r[2]), "=r"(r[3]) : "r"(addr));
}
__device__ __forceinline__ void ldsm_x4_t(uint32_t* r, uint32_t addr) {
    asm volatile("ldmatrix.sync.aligned.m8n8.x4.trans.shared.b16 {%0,%1,%2,%3}, [%4];"
        : "=r"(r[0]), "=r"(r[1]), "=r"(r[2]), "=r"(r[3]) : "r"(addr));
}
__device__ __forceinline__ uint32_t pack_h2(float a, float b) {
    __half2 h = __floats2half2_rn(a, b);
    return *(uint32_t*)&h;
}

// ============================================================================
// GEMM config. A tile [128 m][64 k] (LDH=72); B tile [64 k][128 n] (LDB=136),
// read with trans-LDSM so W stays in its original [K][N] layout.
// ============================================================================
#define NSTAGE 3
#define KCH 64
#define LDH 72
#define LDB 136
#define STAGE_A_B (128 * LDH * 2)      // 18432 B
#define STAGE_B_B (64 * LDB * 2)       // 17408 B
#define GEMM_SMEM_BYTES (NSTAGE * (STAGE_A_B + STAGE_B_B))   // 107520 B

// Mainloop macro: acc[4][4][4] for 128x128 tile at (m0, n0).
// A: [M][K] half row-major. W: [K][N] half row-major (original layout).
#define GEMM_MAINLOOP(Aptr, Wptr, Kdim, Ndim)                                    \
    extern __shared__ __half hsm[];                                             \
    __half* As = hsm;                                                           \
    __half* Bs = hsm + NSTAGE * (STAGE_A_B / 2);                                \
    const int tid  = threadIdx.x;                                               \
    const int wid  = tid >> 5;                                                  \
    const int lane = tid & 31;                                                  \
    const int wm = wid >> 2;                                                    \
    const int wn = wid & 3;                                                     \
    const int qr = lane >> 2;                                                   \
    const int qc = lane & 3;                                                    \
    const int m0 = blockIdx.y * 128;                                            \
    const int n0 = blockIdx.x * 128;                                            \
    const int lrow = lane & 15;                                                 \
    const int lcol = (lane >> 4) * 8;                                           \
    const int rowA = tid >> 3;                                                  \
    const int cA   = (tid & 7) << 3;                                            \
    const int rowB = tid >> 4;                                                  \
    const int cB   = (tid & 15) << 3;                                           \
    const __half* srcA = (Aptr) + (size_t)(m0 + rowA) * (Kdim) + cA;            \
    const __half* srcB = (Wptr) + (size_t)rowB * (Ndim) + n0 + cB;              \
    const uint32_t dA0 = smem_u32(As) + (uint32_t)(rowA * LDH + cA) * 2u;       \
    const uint32_t dB0 = smem_u32(Bs) + (uint32_t)(rowB * LDB + cB) * 2u;       \
    const size_t gRowA = (size_t)32 * (Kdim);                                   \
    const size_t gRowB = (size_t)16 * (Ndim);                                   \
    const uint32_t sRowA = 32u * LDH * 2u;                                      \
    const uint32_t sRowB = 16u * LDB * 2u;                                      \
    uint32_t aAddr[4], bAddr[2];                                                \
    _Pragma("unroll")                                                           \
    for (int mt = 0; mt < 4; ++mt)                                              \
        aAddr[mt] = smem_u32(As) + (uint32_t)((wm * 64 + mt * 16 + lrow) * LDH + lcol) * 2u; \
    _Pragma("unroll")                                                           \
    for (int g = 0; g < 2; ++g)                                                 \
        bAddr[g] = smem_u32(Bs) + (uint32_t)(lrow * LDB + wn * 32 + g * 16 + lcol) * 2u; \
    float acc[4][4][4];                                                         \
    _Pragma("unroll")                                                           \
    for (int i = 0; i < 4; ++i)                                                 \
        _Pragma("unroll")                                                       \
        for (int j = 0; j < 4; ++j)                                             \
            _Pragma("unroll")                                                   \
            for (int k = 0; k < 4; ++k) acc[i][j][k] = 0.0f;                    \
    auto load_chunk = [&](const __half* pA, const __half* pB, int si) {         \
        const uint32_t oA = (uint32_t)si * STAGE_A_B;                           \
        const uint32_t oB = (uint32_t)si * STAGE_B_B;                           \
        _Pragma("unroll")                                                       \
        for (int it = 0; it < 4; ++it) {                                        \
            asm volatile("cp.async.cg.shared.global [%0], [%1], 16;"            \
                :: "r"(dA0 + oA + it * sRowA), "l"(pA + it * gRowA) : "memory");\
            asm volatile("cp.async.cg.shared.global [%0], [%1], 16;"            \
                :: "r"(dB0 + oB + it * sRowB), "l"(pB + it * gRowB) : "memory");\
        }                                                                       \
        asm volatile("cp.async.commit_group;" ::: "memory");                    \
    };                                                                          \
    const int NCH = (Kdim) / KCH;                                               \
    load_chunk(srcA, srcB, 0);                                                  \
    srcA += KCH; srcB += (size_t)KCH * (Ndim);                                  \
    load_chunk(srcA, srcB, 1);                                                  \
    srcA += KCH; srcB += (size_t)KCH * (Ndim);                                  \
    int sCi = 0, sLi = 2;                                                       \
    for (int c = 0; c < NCH; ++c) {                                             \
        if (c + 1 < NCH) { asm volatile("cp.async.wait_group 1;" ::: "memory"); }\
        else             { asm volatile("cp.async.wait_group 0;" ::: "memory"); }\
        __syncthreads();                                                        \
        if (c + 2 < NCH) {                                                      \
            load_chunk(srcA, srcB, sLi);                                        \
            srcA += KCH; srcB += (size_t)KCH * (Ndim);                          \
            if (++sLi == NSTAGE) sLi = 0;                                       \
        }                                                                       \
        _Pragma("unroll")                                                       \
        for (int ks = 0; ks < 4; ++ks) {                                        \
            const uint32_t kOffA = (uint32_t)sCi * STAGE_A_B + (uint32_t)(ks * 32); \
            const uint32_t kOffB = (uint32_t)sCi * STAGE_B_B + (uint32_t)(ks * 16) * LDB * 2u; \
            uint32_t af[4][4];                                                  \
            _Pragma("unroll")                                                   \
            for (int mt = 0; mt < 4; ++mt)                                      \
                ldsm_x4(af[mt], aAddr[mt] + kOffA);                             \
            uint32_t bf[2][4];                                                  \
            _Pragma("unroll")                                                   \
            for (int g = 0; g < 2; ++g)                                         \
                ldsm_x4_t(bf[g], bAddr[g] + kOffB);                             \
            _Pragma("unroll")                                                   \
            for (int mt = 0; mt < 4; ++mt)                                      \
                _Pragma("unroll")                                               \
                for (int g = 0; g < 2; ++g) {                                   \
                    mma_f16(acc[mt][2 * g    ], af[mt], bf[g][0], bf[g][1]);    \
                    mma_f16(acc[mt][2 * g + 1], af[mt], bf[g][2], bf[g][3]);    \
                }                                                               \
        }                                                                       \
        if (++sCi == NSTAGE) sCi = 0;                                           \
    }

// ============================================================================
// Kernel A: QKV GEMM with FUSED bias + RoPE + split epilogue.
// ============================================================================
__global__ void __launch_bounds__(256, 2) gemm_qkv_rope(
    const __half* __restrict__ A, const __half* __restrict__ W,
    const float* __restrict__ bias,
    const float* __restrict__ cosb, const float* __restrict__ sinb)
{
    GEMM_MAINLOOP(A, W, HIDDEN, QKV_N)

    const int col0 = n0 + wn * 32;
    const int which = col0 >> 11;              // 0=q, 1=k, 2=v
    const int hd = (col0 & 2047) >> 7;
    const int d0 = col0 & 127;
    __half* outBase = (which == 0) ? g_qh : (which == 1) ? g_kh : g_vh;
    const bool ropez = (d0 == 0) && (which < 2);
    const float qs = (which == 0) ? 0.08838834764831845f : 1.0f;

#pragma unroll
    for (int mt = 0; mt < 4; ++mt) {
        const int t0 = m0 + wm * 64 + mt * 16 + qr;
        const int t1 = t0 + 8;

        float vals[4][4];
#pragma unroll
        for (int nt = 0; nt < 4; ++nt) {
            const int col = col0 + nt * 8 + 2 * qc;
            const float2 bv = *(const float2*)&bias[col];
            vals[nt][0] = acc[mt][nt][0] + bv.x;
            vals[nt][1] = acc[mt][nt][1] + bv.y;
            vals[nt][2] = acc[mt][nt][2] + bv.x;
            vals[nt][3] = acc[mt][nt][3] + bv.y;
        }

        if (ropez) {
#pragma unroll
            for (int nt = 0; nt < 2; ++nt) {
                const int r = nt * 8 + 2 * qc;
                const float c0a = cosb[t0 * ROT + r],     s0a = sinb[t0 * ROT + r];
                const float c0b = cosb[t0 * ROT + r + 1], s0b = sinb[t0 * ROT + r + 1];
                const float c1a = cosb[t1 * ROT + r],     s1a = sinb[t1 * ROT + r];
                const float c1b = cosb[t1 * ROT + r + 1], s1b = sinb[t1 * ROT + r + 1];
                float x1, x2;
                x1 = vals[nt][0]; x2 = vals[nt + 2][0];
                vals[nt][0] = x1 * c0a - x2 * s0a; vals[nt + 2][0] = x1 * s0a + x2 * c0a;
                x1 = vals[nt][1]; x2 = vals[nt + 2][1];
                vals[nt][1] = x1 * c0b - x2 * s0b; vals[nt + 2][1] = x1 * s0b + x2 * c0b;
                x1 = vals[nt][2]; x2 = vals[nt + 2][2];
                vals[nt][2] = x1 * c1a - x2 * s1a; vals[nt + 2][2] = x1 * s1a + x2 * c1a;
                x1 = vals[nt][3]; x2 = vals[nt + 2][3];
                vals[nt][3] = x1 * c1b - x2 * s1b; vals[nt + 2][3] = x1 * s1b + x2 * c1b;
            }
        }

        const int b0i = t0 >> 10, s0i = t0 & 1023;
        const int b1i = t1 >> 10, s1i = t1 & 1023;
        const size_t base0 = ((size_t)(b0i * NUM_HEADS + hd) * SEQ + s0i) * HEAD_SIZE;
        const size_t base1 = ((size_t)(b1i * NUM_HEADS + hd) * SEQ + s1i) * HEAD_SIZE;
#pragma unroll
        for (int nt = 0; nt < 4; ++nt) {
            const int d = d0 + nt * 8 + 2 * qc;
            *(__half2*)&outBase[base0 + d] =
                __floats2half2_rn(vals[nt][0] * qs, vals[nt][1] * qs);
            *(__half2*)&outBase[base1 + d] =
                __floats2half2_rn(vals[nt][2] * qs, vals[nt][3] * qs);
        }
    }
}

// ============================================================================
// Kernel B: dense GEMM (fp32 output + bias)
// ============================================================================
__global__ void __launch_bounds__(256, 2) gemm_dense(
    const __half* __restrict__ A, const __half* __restrict__ W,
    const float* __restrict__ bias, float* __restrict__ Cf)
{
    GEMM_MAINLOOP(A, W, HIDDEN, HIDDEN)

#pragma unroll
    for (int mt = 0; mt < 4; ++mt) {
        const int row = m0 + wm * 64 + mt * 16 + qr;
#pragma unroll
        for (int nt = 0; nt < 4; ++nt) {
            const int col = n0 + wn * 32 + nt * 8 + 2 * qc;
            const float2 bv = *(const float2*)&bias[col];
            *(float2*)&Cf[(size_t)row * HIDDEN + col] =
                make_float2(acc[mt][nt][0] + bv.x, acc[mt][nt][1] + bv.y);
            *(float2*)&Cf[(size_t)(row + 8) * HIDDEN + col] =
                make_float2(acc[mt][nt][2] + bv.x, acc[mt][nt][3] + bv.y);
        }
    }
}

// ============================================================================
// float -> half bulk convert
// ============================================================================
__global__ void __launch_bounds__(256) f2h_copy(
    const float* __restrict__ src, __half* __restrict__ dst, int n4)
{
    const int i = blockIdx.x * 256 + threadIdx.x;
    if (i < n4) {
        float4 v = ((const float4*)src)[i];
        ((__half2*)dst)[2 * i]     = __floats2half2_rn(v.x, v.y);
        ((__half2*)dst)[2 * i + 1] = __floats2half2_rn(v.z, v.w);
    }
}

// ============================================================================
// flash attention v6 — register softmax + trans-LDSM V (no V transpose pass).
// Block 128 thr = 4 warps; warp w owns rows w*16..+15. V tile read [s][d].
// ============================================================================
#define FQT 64
#define FKT 64
#define LDK 136

struct Flash6Smem {
    __half Qs[FQT][LDK];             // 17408 B
    __half Ks[2][FKT][LDK];          // 34816 B
    __half Vs[2][FKT][LDK];          // 34816 B  ([s][d], d-contiguous)
};                                    // 87040 B

__global__ void __launch_bounds__(128) flash_f16_v6()
{
    extern __shared__ char sraw[];
    Flash6Smem& S = *reinterpret_cast<Flash6Smem*>(sraw);

    const int qt = blockIdx.x;
    const int h  = blockIdx.y;
    const int b  = blockIdx.z;
    const int tid  = threadIdx.x;
    const int wid  = tid >> 5;
    const int lane = tid & 31;
    const int qr = lane >> 2;
    const int qc = lane & 3;
    const int lrow = lane & 15;
    const int lcol = (lane >> 4) * 8;
    const int m0 = wid * 16;
    const int bh = b * NUM_HEADS + h;
    const size_t headbase = (size_t)bh * SEQ * HEAD_SIZE;

    {
        const __half* qg = g_qh + headbase + (size_t)(qt * FQT) * HEAD_SIZE;
#pragma unroll
        for (int it = 0; it < 8; ++it) {
            const int flat = it * 128 + tid;
            const int r = flat >> 4;
            const int c = (flat & 15) << 3;
            *(uint4*)&S.Qs[r][c] = *(const uint4*)(qg + (size_t)r * HEAD_SIZE + c);
        }
    }

    auto issue_tile = [&](int kt, int buf) {
        const __half* kg = g_kh + headbase + (size_t)(kt * FKT) * HEAD_SIZE;
        const __half* vg = g_vh + headbase + (size_t)(kt * FKT) * HEAD_SIZE;
        const uint32_t kd = smem_u32(&S.Ks[buf][0][0]);
        const uint32_t vd = smem_u32(&S.Vs[buf][0][0]);
#pragma unroll
        for (int it = 0; it < 8; ++it) {
            const int flat = it * 128 + tid;
            const int r = flat >> 4;
            const int c = (flat & 15) << 3;
            const uint32_t so = (uint32_t)(r * LDK + c) * 2u;
            const size_t go = (size_t)r * HEAD_SIZE + c;
            asm volatile("cp.async.cg.shared.global [%0], [%1], 16;"
                :: "r"(kd + so), "l"(kg + go) : "memory");
            asm volatile("cp.async.cg.shared.global [%0], [%1], 16;"
                :: "r"(vd + so), "l"(vg + go) : "memory");
        }
        asm volatile("cp.async.commit_group;" ::: "memory");
    };

    const int nkt = qt + 1;
    issue_tile(0, 0);
    __syncthreads();

    uint32_t qf[8][4];
#pragma unroll
    for (int ks = 0; ks < 8; ++ks)
        ldsm_x4(qf[ks], smem_u32(&S.Qs[m0 + lrow][ks * 16 + lcol]));

    float m0r = -1e30f, m1r = -1e30f, l0r = 0.0f, l1r = 0.0f;
    float oacc[16][4];
#pragma unroll
    for (int i = 0; i < 16; ++i)
#pragma unroll
        for (int j = 0; j < 4; ++j) oacc[i][j] = 0.0f;

    int bufC = 0;
    for (int kt = 0; kt < nkt; ++kt) {
        __syncthreads();
        if (kt + 1 < nkt) {
            issue_tile(kt + 1, bufC ^ 1);
            asm volatile("cp.async.wait_group 1;" ::: "memory");
        } else {
            asm volatile("cp.async.wait_group 0;" ::: "memory");
        }
        __syncthreads();

        // ---- score ----
        float sacc[8][4];
#pragma unroll
        for (int i = 0; i < 8; ++i)
#pragma unroll
            for (int j = 0; j < 4; ++j) sacc[i][j] = 0.0f;
        {
            const uint32_t kBase = smem_u32(&S.Ks[bufC][lrow][lcol]);
#pragma unroll
            for (int ks = 0; ks < 8; ++ks) {
#pragma unroll
                for (int nt2 = 0; nt2 < 4; ++nt2) {
                    uint32_t bf[4];
                    ldsm_x4(bf, kBase + (uint32_t)(nt2 * 16 * LDK * 2 + ks * 32));
                    mma_f16(sacc[2 * nt2    ], qf[ks], bf[0], bf[2]);
                    mma_f16(sacc[2 * nt2 + 1], qf[ks], bf[1], bf[3]);
                }
            }
        }

        if (kt == qt) {
            const int lr0 = m0 + qr;
            const int lr1 = m0 + qr + 8;
#pragma unroll
            for (int nt = 0; nt < 8; ++nt) {
                const int lc = nt * 8 + 2 * qc;
                if (lc     > lr0) sacc[nt][0] = -1e30f;
                if (lc + 1 > lr0) sacc[nt][1] = -1e30f;
                if (lc     > lr1) sacc[nt][2] = -1e30f;
                if (lc + 1 > lr1) sacc[nt][3] = -1e30f;
            }
        }

        // ---- in-register online softmax ----
        float mx0 = -1e30f, mx1 = -1e30f;
#pragma unroll
        for (int nt = 0; nt < 8; ++nt) {
            mx0 = fmaxf(mx0, fmaxf(sacc[nt][0], sacc[nt][1]));
            mx1 = fmaxf(mx1, fmaxf(sacc[nt][2], sacc[nt][3]));
        }
        mx0 = fmaxf(mx0, __shfl_xor_sync(0xffffffffu, mx0, 1));
        mx0 = fmaxf(mx0, __shfl_xor_sync(0xffffffffu, mx0, 2));
        mx1 = fmaxf(mx1, __shfl_xor_sync(0xffffffffu, mx1, 1));
        mx1 = fmaxf(mx1, __shfl_xor_sync(0xffffffffu, mx1, 2));

        const float mn0 = fmaxf(m0r, mx0);
        const float mn1 = fmaxf(m1r, mx1);
        const float a0 = __expf(m0r - mn0);
        const float a1 = __expf(m1r - mn1);
        m0r = mn0; m1r = mn1;

        float s0 = 0.0f, s1 = 0.0f;
        uint32_t pf[4][4];
#pragma unroll
        for (int k2 = 0; k2 < 4; ++k2) {
            const float pa0 = __expf(sacc[2 * k2][0] - mn0);
            const float pa1 = __expf(sacc[2 * k2][1] - mn0);
            const float pb0 = __expf(sacc[2 * k2][2] - mn1);
            const float pb1 = __expf(sacc[2 * k2][3] - mn1);
            const float pc0 = __expf(sacc[2 * k2 + 1][0] - mn0);
            const float pc1 = __expf(sacc[2 * k2 + 1][1] - mn0);
            const float pd0 = __expf(sacc[2 * k2 + 1][2] - mn1);
            const float pd1 = __expf(sacc[2 * k2 + 1][3] - mn1);
            s0 += pa0 + pa1 + pc0 + pc1;
            s1 += pb0 + pb1 + pd0 + pd1;
            pf[k2][0] = pack_h2(pa0, pa1);
            pf[k2][1] = pack_h2(pb0, pb1);
            pf[k2][2] = pack_h2(pc0, pc1);
            pf[k2][3] = pack_h2(pd0, pd1);
        }
        s0 += __shfl_xor_sync(0xffffffffu, s0, 1);
        s0 += __shfl_xor_sync(0xffffffffu, s0, 2);
        s1 += __shfl_xor_sync(0xffffffffu, s1, 1);
        s1 += __shfl_xor_sync(0xffffffffu, s1, 2);
        l0r = l0r * a0 + s0;
        l1r = l1r * a1 + s1;

        // ---- rescale + PV with trans-LDSM from V [s][d] ----
#pragma unroll
        for (int nt = 0; nt < 16; ++nt) {
            oacc[nt][0] *= a0; oacc[nt][1] *= a0;
            oacc[nt][2] *= a1; oacc[nt][3] *= a1;
        }
        {
            const uint32_t vBase = smem_u32(&S.Vs[bufC][lrow][lcol]);
#pragma unroll
            for (int k2 = 0; k2 < 4; ++k2) {
                const uint32_t kOff = (uint32_t)(k2 * 16 * LDK * 2);
#pragma unroll
                for (int nt2 = 0; nt2 < 8; ++nt2) {
                    uint32_t bf[4];
                    ldsm_x4_t(bf, vBase + kOff + (uint32_t)(nt2 * 16 * 2));
                    mma_f16(oacc[2 * nt2    ], pf[k2], bf[0], bf[1]);
                    mma_f16(oacc[2 * nt2 + 1], pf[k2], bf[2], bf[3]);
                }
            }
        }
        bufC ^= 1;
    }

    {
        const int t0 = b * SEQ + qt * FQT;
        const float inv0 = 1.0f / l0r;
        const float inv1 = 1.0f / l1r;
        const int row0 = t0 + m0 + qr;
#pragma unroll
        for (int nt = 0; nt < 16; ++nt) {
            const int col = h * HEAD_SIZE + nt * 8 + 2 * qc;
            *(__half2*)&g_attnh[(size_t)row0 * HIDDEN + col] =
                __floats2half2_rn(oacc[nt][0] * inv0, oacc[nt][1] * inv0);
            *(__half2*)&g_attnh[(size_t)(row0 + 8) * HIDDEN + col] =
                __floats2half2_rn(oacc[nt][2] * inv1, oacc[nt][3] * inv1);
        }
    }
}

// ============================================================================
// launch
// ============================================================================
extern "C" void kernel_launch(void* const* d_in, const int* in_sizes, int n_in,
                              void* d_out, int out_size)
{
    const float* hidden  = (const float*)d_in[0];
    const float* cosb    = (const float*)d_in[1];
    const float* sinb    = (const float*)d_in[2];
    const float* W_qkv   = (const float*)d_in[3];
    const float* b_qkv   = (const float*)d_in[4];
    const float* W_dense = (const float*)d_in[5];
    const float* b_dense = (const float*)d_in[6];
    float* out = (float*)d_out;

    __half *attnh_ptr, *hidh_ptr, *wqkvh_ptr, *wdenseh_ptr;
    cudaGetSymbolAddress((void**)&attnh_ptr, g_attnh);
    cudaGetSymbolAddress((void**)&hidh_ptr, g_hidh);
    cudaGetSymbolAddress((void**)&wqkvh_ptr, g_wqkvh);
    cudaGetSymbolAddress((void**)&wdenseh_ptr, g_wdenseh);

    cudaFuncSetAttribute(flash_f16_v6, cudaFuncAttributeMaxDynamicSharedMemorySize,
                         (int)sizeof(Flash6Smem));
    cudaFuncSetAttribute(gemm_qkv_rope, cudaFuncAttributeMaxDynamicSharedMemorySize,
                         GEMM_SMEM_BYTES);
    cudaFuncSetAttribute(gemm_dense, cudaFuncAttributeMaxDynamicSharedMemorySize,
                         GEMM_SMEM_BYTES);

    // 0) operand prep: straight f2h on A and both weights (no transposes)
    {
        int n4 = TOTAL * HIDDEN / 4;
        f2h_copy<<<(n4 + 255) / 256, 256>>>(hidden, hidh_ptr, n4);
        n4 = HIDDEN * QKV_N / 4;
        f2h_copy<<<(n4 + 255) / 256, 256>>>(W_qkv, wqkvh_ptr, n4);
        n4 = HIDDEN * HIDDEN / 4;
        f2h_copy<<<(n4 + 255) / 256, 256>>>(W_dense, wdenseh_ptr, n4);
    }
    // 1) QKV projection with fused bias+RoPE+split epilogue (trans-LDSM B)
    gemm_qkv_rope<<<dim3(QKV_N / 128, TOTAL / 128), 256, GEMM_SMEM_BYTES>>>(
        hidh_ptr, wqkvh_ptr, b_qkv, cosb, sinb);
    // 2) causal flash attention v6 (trans-LDSM V; no V transpose pass)
    flash_f16_v6<<<dim3(SEQ / FQT, NUM_HEADS, BATCH), 128, sizeof(Flash6Smem)>>>();
    // 3) dense projection (fp32 output)
    gemm_dense<<<dim3(HIDDEN / 128, TOTAL / 128), 256, GEMM_SMEM_BYTES>>>(
        attnh_ptr, wdenseh_ptr, b_dense, out);
}

// round 14
// speedup vs baseline: 1.3010x; 1.0152x over previous
#include <cuda_runtime.h>
#include <cuda.h>
#include <cuda_fp16.h>
#include <math.h>
#include <stdint.h>

// Problem constants
#define NUM_HEADS 16
#define HEAD_SIZE 128
#define HIDDEN    2048
#define ROT       16
#define BATCH     4
#define SEQ       1024
#define TOTAL     4096
#define QKV_N     6144

// -------- device scratch --------
__device__ __half g_qh[(size_t)TOTAL * HIDDEN];        // Q half, pre-scaled, [B,H,S,D]
__device__ __half g_kh[(size_t)TOTAL * HIDDEN];        // K half, [B,H,S,D]
__device__ __half g_vh[(size_t)TOTAL * HIDDEN];        // V half, [B,H,S,D]
__device__ __half g_attnh[(size_t)TOTAL * HIDDEN];     // flash output (half)
__device__ __half g_hidh[(size_t)TOTAL * HIDDEN];      // hidden states (half)
__device__ __half g_wqkvh[(size_t)HIDDEN * QKV_N];     // W_qkv [K][N] half (orig layout)
__device__ __half g_wdenseh[(size_t)HIDDEN * HIDDEN];  // W_dense [K][N] half

// ============================================================================
// helpers
// ============================================================================
__device__ __forceinline__ uint32_t smem_u32(const void* p) {
    uint32_t a;
    asm("{ .reg .u64 t; cvta.to.shared.u64 t, %1; cvt.u32.u64 %0, t; }" : "=r"(a) : "l"(p));
    return a;
}
__device__ __forceinline__ void mma_f16(float* c, const uint32_t* a, uint32_t b0, uint32_t b1) {
    asm volatile(
        "mma.sync.aligned.m16n8k16.row.col.f32.f16.f16.f32 "
        "{%0,%1,%2,%3}, {%4,%5,%6,%7}, {%8,%9}, {%0,%1,%2,%3};"
        : "+f"(c[0]), "+f"(c[1]), "+f"(c[2]), "+f"(c[3])
        : "r"(a[0]), "r"(a[1]), "r"(a[2]), "r"(a[3]), "r"(b0), "r"(b1));
}
__device__ __forceinline__ void ldsm_x4(uint32_t* r, uint32_t addr) {
    asm volatile("ldmatrix.sync.aligned.m8n8.x4.shared.b16 {%0,%1,%2,%3}, [%4];"
        : "=r"(r[0]), "=r"(r[1]), "=r"(r[2]), "=r"(r[3]) : "r"(addr));
}
__device__ __forceinline__ void ldsm_x4_t(uint32_t* r, uint32_t addr) {
    asm volatile("ldmatrix.sync.aligned.m8n8.x4.trans.shared.b16 {%0,%1,%2,%3}, [%4];"
        : "=r"(r[0]), "=r"(r[1]), "=r"(r[2]), "=r"(r[3]) : "r"(addr));
}
__device__ __forceinline__ uint32_t pack_h2(float a, float b) {
    __half2 h = __floats2half2_rn(a, b);
    return *(uint32_t*)&h;
}

// ============================================================================
// GEMM config (unchanged from round-13 validated version)
// ============================================================================
#define NSTAGE 3
#define KCH 64
#define LDH 72
#define LDB 136
#define STAGE_A_B (128 * LDH * 2)      // 18432 B
#define STAGE_B_B (64 * LDB * 2)       // 17408 B
#define GEMM_SMEM_BYTES (NSTAGE * (STAGE_A_B + STAGE_B_B))   // 107520 B

#define GEMM_MAINLOOP(Aptr, Wptr, Kdim, Ndim)                                    \
    extern __shared__ __half hsm[];                                             \
    __half* As = hsm;                                                           \
    __half* Bs = hsm + NSTAGE * (STAGE_A_B / 2);                                \
    const int tid  = threadIdx.x;                                               \
    const int wid  = tid >> 5;                                                  \
    const int lane = tid & 31;                                                  \
    const int wm = wid >> 2;                                                    \
    const int wn = wid & 3;                                                     \
    const int qr = lane >> 2;                                                   \
    const int qc = lane & 3;                                                    \
    const int m0 = blockIdx.y * 128;                                            \
    const int n0 = blockIdx.x * 128;                                            \
    const int lrow = lane & 15;                                                 \
    const int lcol = (lane >> 4) * 8;                                           \
    const int rowA = tid >> 3;                                                  \
    const int cA   = (tid & 7) << 3;                                            \
    const int rowB = tid >> 4;                                                  \
    const int cB   = (tid & 15) << 3;                                           \
    const __half* srcA = (Aptr) + (size_t)(m0 + rowA) * (Kdim) + cA;            \
    const __half* srcB = (Wptr) + (size_t)rowB * (Ndim) + n0 + cB;              \
    const uint32_t dA0 = smem_u32(As) + (uint32_t)(rowA * LDH + cA) * 2u;       \
    const uint32_t dB0 = smem_u32(Bs) + (uint32_t)(rowB * LDB + cB) * 2u;       \
    const size_t gRowA = (size_t)32 * (Kdim);                                   \
    const size_t gRowB = (size_t)16 * (Ndim);                                   \
    const uint32_t sRowA = 32u * LDH * 2u;                                      \
    const uint32_t sRowB = 16u * LDB * 2u;                                      \
    uint32_t aAddr[4], bAddr[2];                                                \
    _Pragma("unroll")                                                           \
    for (int mt = 0; mt < 4; ++mt)                                              \
        aAddr[mt] = smem_u32(As) + (uint32_t)((wm * 64 + mt * 16 + lrow) * LDH + lcol) * 2u; \
    _Pragma("unroll")                                                           \
    for (int g = 0; g < 2; ++g)                                                 \
        bAddr[g] = smem_u32(Bs) + (uint32_t)(lrow * LDB + wn * 32 + g * 16 + lcol) * 2u; \
    float acc[4][4][4];                                                         \
    _Pragma("unroll")                                                           \
    for (int i = 0; i < 4; ++i)                                                 \
        _Pragma("unroll")                                                       \
        for (int j = 0; j < 4; ++j)                                             \
            _Pragma("unroll")                                                   \
            for (int k = 0; k < 4; ++k) acc[i][j][k] = 0.0f;                    \
    auto load_chunk = [&](const __half* pA, const __half* pB, int si) {         \
        const uint32_t oA = (uint32_t)si * STAGE_A_B;                           \
        const uint32_t oB = (uint32_t)si * STAGE_B_B;                           \
        _Pragma("unroll")                                                       \
        for (int it = 0; it < 4; ++it) {                                        \
            asm volatile("cp.async.cg.shared.global [%0], [%1], 16;"            \
                :: "r"(dA0 + oA + it * sRowA), "l"(pA + it * gRowA) : "memory");\
            asm volatile("cp.async.cg.shared.global [%0], [%1], 16;"            \
                :: "r"(dB0 + oB + it * sRowB), "l"(pB + it * gRowB) : "memory");\
        }                                                                       \
        asm volatile("cp.async.commit_group;" ::: "memory");                    \
    };                                                                          \
    const int NCH = (Kdim) / KCH;                                               \
    load_chunk(srcA, srcB, 0);                                                  \
    srcA += KCH; srcB += (size_t)KCH * (Ndim);                                  \
    load_chunk(srcA, srcB, 1);                                                  \
    srcA += KCH; srcB += (size_t)KCH * (Ndim);                                  \
    int sCi = 0, sLi = 2;                                                       \
    for (int c = 0; c < NCH; ++c) {                                             \
        if (c + 1 < NCH) { asm volatile("cp.async.wait_group 1;" ::: "memory"); }\
        else             { asm volatile("cp.async.wait_group 0;" ::: "memory"); }\
        __syncthreads();                                                        \
        if (c + 2 < NCH) {                                                      \
            load_chunk(srcA, srcB, sLi);                                        \
            srcA += KCH; srcB += (size_t)KCH * (Ndim);                          \
            if (++sLi == NSTAGE) sLi = 0;                                       \
        }                                                                       \
        _Pragma("unroll")                                                       \
        for (int ks = 0; ks < 4; ++ks) {                                        \
            const uint32_t kOffA = (uint32_t)sCi * STAGE_A_B + (uint32_t)(ks * 32); \
            const uint32_t kOffB = (uint32_t)sCi * STAGE_B_B + (uint32_t)(ks * 16) * LDB * 2u; \
            uint32_t af[4][4];                                                  \
            _Pragma("unroll")                                                   \
            for (int mt = 0; mt < 4; ++mt)                                      \
                ldsm_x4(af[mt], aAddr[mt] + kOffA);                             \
            uint32_t bf[2][4];                                                  \
            _Pragma("unroll")                                                   \
            for (int g = 0; g < 2; ++g)                                         \
                ldsm_x4_t(bf[g], bAddr[g] + kOffB);                             \
            _Pragma("unroll")                                                   \
            for (int mt = 0; mt < 4; ++mt)                                      \
                _Pragma("unroll")                                               \
                for (int g = 0; g < 2; ++g) {                                   \
                    mma_f16(acc[mt][2 * g    ], af[mt], bf[g][0], bf[g][1]);    \
                    mma_f16(acc[mt][2 * g + 1], af[mt], bf[g][2], bf[g][3]);    \
                }                                                               \
        }                                                                       \
        if (++sCi == NSTAGE) sCi = 0;                                           \
    }

// ============================================================================
// Kernel A: QKV GEMM with FUSED bias + RoPE + split epilogue. (unchanged)
// ============================================================================
__global__ void __launch_bounds__(256, 2) gemm_qkv_rope(
    const __half* __restrict__ A, const __half* __restrict__ W,
    const float* __restrict__ bias,
    const float* __restrict__ cosb, const float* __restrict__ sinb)
{
    GEMM_MAINLOOP(A, W, HIDDEN, QKV_N)

    const int col0 = n0 + wn * 32;
    const int which = col0 >> 11;              // 0=q, 1=k, 2=v
    const int hd = (col0 & 2047) >> 7;
    const int d0 = col0 & 127;
    __half* outBase = (which == 0) ? g_qh : (which == 1) ? g_kh : g_vh;
    const bool ropez = (d0 == 0) && (which < 2);
    const float qs = (which == 0) ? 0.08838834764831845f : 1.0f;

#pragma unroll
    for (int mt = 0; mt < 4; ++mt) {
        const int t0 = m0 + wm * 64 + mt * 16 + qr;
        const int t1 = t0 + 8;

        float vals[4][4];
#pragma unroll
        for (int nt = 0; nt < 4; ++nt) {
            const int col = col0 + nt * 8 + 2 * qc;
            const float2 bv = *(const float2*)&bias[col];
            vals[nt][0] = acc[mt][nt][0] + bv.x;
            vals[nt][1] = acc[mt][nt][1] + bv.y;
            vals[nt][2] = acc[mt][nt][2] + bv.x;
            vals[nt][3] = acc[mt][nt][3] + bv.y;
        }

        if (ropez) {
#pragma unroll
            for (int nt = 0; nt < 2; ++nt) {
                const int r = nt * 8 + 2 * qc;
                const float c0a = cosb[t0 * ROT + r],     s0a = sinb[t0 * ROT + r];
                const float c0b = cosb[t0 * ROT + r + 1], s0b = sinb[t0 * ROT + r + 1];
                const float c1a = cosb[t1 * ROT + r],     s1a = sinb[t1 * ROT + r];
                const float c1b = cosb[t1 * ROT + r + 1], s1b = sinb[t1 * ROT + r + 1];
                float x1, x2;
                x1 = vals[nt][0]; x2 = vals[nt + 2][0];
                vals[nt][0] = x1 * c0a - x2 * s0a; vals[nt + 2][0] = x1 * s0a + x2 * c0a;
                x1 = vals[nt][1]; x2 = vals[nt + 2][1];
                vals[nt][1] = x1 * c0b - x2 * s0b; vals[nt + 2][1] = x1 * s0b + x2 * c0b;
                x1 = vals[nt][2]; x2 = vals[nt + 2][2];
                vals[nt][2] = x1 * c1a - x2 * s1a; vals[nt + 2][2] = x1 * s1a + x2 * c1a;
                x1 = vals[nt][3]; x2 = vals[nt + 2][3];
                vals[nt][3] = x1 * c1b - x2 * s1b; vals[nt + 2][3] = x1 * s1b + x2 * c1b;
            }
        }

        const int b0i = t0 >> 10, s0i = t0 & 1023;
        const int b1i = t1 >> 10, s1i = t1 & 1023;
        const size_t base0 = ((size_t)(b0i * NUM_HEADS + hd) * SEQ + s0i) * HEAD_SIZE;
        const size_t base1 = ((size_t)(b1i * NUM_HEADS + hd) * SEQ + s1i) * HEAD_SIZE;
#pragma unroll
        for (int nt = 0; nt < 4; ++nt) {
            const int d = d0 + nt * 8 + 2 * qc;
            *(__half2*)&outBase[base0 + d] =
                __floats2half2_rn(vals[nt][0] * qs, vals[nt][1] * qs);
            *(__half2*)&outBase[base1 + d] =
                __floats2half2_rn(vals[nt][2] * qs, vals[nt][3] * qs);
        }
    }
}

// ============================================================================
// Kernel B: dense GEMM (fp32 output + bias) (unchanged)
// ============================================================================
__global__ void __launch_bounds__(256, 2) gemm_dense(
    const __half* __restrict__ A, const __half* __restrict__ W,
    const float* __restrict__ bias, float* __restrict__ Cf)
{
    GEMM_MAINLOOP(A, W, HIDDEN, HIDDEN)

#pragma unroll
    for (int mt = 0; mt < 4; ++mt) {
        const int row = m0 + wm * 64 + mt * 16 + qr;
#pragma unroll
        for (int nt = 0; nt < 4; ++nt) {
            const int col = n0 + wn * 32 + nt * 8 + 2 * qc;
            const float2 bv = *(const float2*)&bias[col];
            *(float2*)&Cf[(size_t)row * HIDDEN + col] =
                make_float2(acc[mt][nt][0] + bv.x, acc[mt][nt][1] + bv.y);
            *(float2*)&Cf[(size_t)(row + 8) * HIDDEN + col] =
                make_float2(acc[mt][nt][2] + bv.x, acc[mt][nt][3] + bv.y);
        }
    }
}

// ============================================================================
// Merged f2h prep: one launch converts hidden + W_qkv + W_dense.
// Segment boundaries in float4 units.
// ============================================================================
#define N4_HID   (TOTAL * HIDDEN / 4)           // 2097152
#define N4_WQKV  (HIDDEN * QKV_N / 4)           // 3145728
#define N4_WD    (HIDDEN * HIDDEN / 4)          // 1048576
#define N4_ALL   (N4_HID + N4_WQKV + N4_WD)

__global__ void __launch_bounds__(256) f2h_all(
    const float* __restrict__ hid, const float* __restrict__ wqkv,
    const float* __restrict__ wd)
{
    const int i = blockIdx.x * 256 + threadIdx.x;
    if (i >= N4_ALL) return;
    const float* src;
    __half* dst;
    int j;
    if (i < N4_HID)              { src = hid;  dst = g_hidh;    j = i; }
    else if (i < N4_HID + N4_WQKV) { src = wqkv; dst = g_wqkvh; j = i - N4_HID; }
    else                         { src = wd;   dst = g_wdenseh; j = i - N4_HID - N4_WQKV; }
    float4 v = ((const float4*)src)[j];
    ((__half2*)dst)[2 * j]     = __floats2half2_rn(v.x, v.y);
    ((__half2*)dst)[2 * j + 1] = __floats2half2_rn(v.z, v.w);
}

// ============================================================================
// flash attention v7 — FQT=128 (8 warps), register softmax, trans-LDSM V.
// K/V tiles (64 keys) now serve 128 q-rows: half the traffic and barriers
// per unit MMA work vs v6.
// ============================================================================
#define FQT 128
#define FKT 64
#define LDK 136

struct Flash7Smem {
    __half Qs[FQT][LDK];             // 34816 B
    __half Ks[2][FKT][LDK];          // 34816 B
    __half Vs[2][FKT][LDK];          // 34816 B
};                                    // 104448 B

__global__ void __launch_bounds__(256) flash_f16_v7()
{
    extern __shared__ char sraw[];
    Flash7Smem& S = *reinterpret_cast<Flash7Smem*>(sraw);

    const int qt = blockIdx.x;
    const int h  = blockIdx.y;
    const int b  = blockIdx.z;
    const int tid  = threadIdx.x;
    const int wid  = tid >> 5;         // 0..7
    const int lane = tid & 31;
    const int qr = lane >> 2;
    const int qc = lane & 3;
    const int lrow = lane & 15;
    const int lcol = (lane >> 4) * 8;
    const int m0 = wid * 16;           // warp's row band within 128
    const int bh = b * NUM_HEADS + h;
    const size_t headbase = (size_t)bh * SEQ * HEAD_SIZE;

    // ---- load Q tile (128x128 halves = 2048 uint4, 8 iters of 256) ----
    {
        const __half* qg = g_qh + headbase + (size_t)(qt * FQT) * HEAD_SIZE;
#pragma unroll
        for (int it = 0; it < 8; ++it) {
            const int flat = it * 256 + tid;
            const int r = flat >> 4;
            const int c = (flat & 15) << 3;
            *(uint4*)&S.Qs[r][c] = *(const uint4*)(qg + (size_t)r * HEAD_SIZE + c);
        }
    }

    auto issue_tile = [&](int kt, int buf) {
        const __half* kg = g_kh + headbase + (size_t)(kt * FKT) * HEAD_SIZE;
        const __half* vg = g_vh + headbase + (size_t)(kt * FKT) * HEAD_SIZE;
        const uint32_t kd = smem_u32(&S.Ks[buf][0][0]);
        const uint32_t vd = smem_u32(&S.Vs[buf][0][0]);
#pragma unroll
        for (int it = 0; it < 4; ++it) {
            const int flat = it * 256 + tid;
            const int r = flat >> 4;
            const int c = (flat & 15) << 3;
            const uint32_t so = (uint32_t)(r * LDK + c) * 2u;
            const size_t go = (size_t)r * HEAD_SIZE + c;
            asm volatile("cp.async.cg.shared.global [%0], [%1], 16;"
                :: "r"(kd + so), "l"(kg + go) : "memory");
            asm volatile("cp.async.cg.shared.global [%0], [%1], 16;"
                :: "r"(vd + so), "l"(vg + go) : "memory");
        }
        asm volatile("cp.async.commit_group;" ::: "memory");
    };

    const int nkt = 2 * qt + 2;      // k-tiles covering keys [0, (qt+1)*128)
    issue_tile(0, 0);
    __syncthreads();

    uint32_t qf[8][4];
#pragma unroll
    for (int ks = 0; ks < 8; ++ks)
        ldsm_x4(qf[ks], smem_u32(&S.Qs[m0 + lrow][ks * 16 + lcol]));

    float m0r = -1e30f, m1r = -1e30f, l0r = 0.0f, l1r = 0.0f;
    float oacc[16][4];
#pragma unroll
    for (int i = 0; i < 16; ++i)
#pragma unroll
        for (int j = 0; j < 4; ++j) oacc[i][j] = 0.0f;

    int bufC = 0;
    for (int kt = 0; kt < nkt; ++kt) {
        __syncthreads();
        if (kt + 1 < nkt) {
            issue_tile(kt + 1, bufC ^ 1);
            asm volatile("cp.async.wait_group 1;" ::: "memory");
        } else {
            asm volatile("cp.async.wait_group 0;" ::: "memory");
        }
        __syncthreads();

        // ---- score: S[16x64] per warp ----
        float sacc[8][4];
#pragma unroll
        for (int i = 0; i < 8; ++i)
#pragma unroll
            for (int j = 0; j < 4; ++j) sacc[i][j] = 0.0f;
        {
            const uint32_t kBase = smem_u32(&S.Ks[bufC][lrow][lcol]);
#pragma unroll
            for (int ks = 0; ks < 8; ++ks) {
#pragma unroll
                for (int nt2 = 0; nt2 < 4; ++nt2) {
                    uint32_t bf[4];
                    ldsm_x4(bf, kBase + (uint32_t)(nt2 * 16 * LDK * 2 + ks * 32));
                    mma_f16(sacc[2 * nt2    ], qf[ks], bf[0], bf[2]);
                    mma_f16(sacc[2 * nt2 + 1], qf[ks], bf[1], bf[3]);
                }
            }
        }

        // ---- causal mask: only the last two k-tiles can cross the diagonal.
        // global col = kt*64 + lc ; global row = qt*128 + m0 + qr(+8).
        // mask iff lc + (kt - 2*qt)*64 > m0 + qr.
        if (kt >= 2 * qt) {
            const int moff = (kt - 2 * qt) * 64;
            const int lr0 = m0 + qr;
            const int lr1 = m0 + qr + 8;
#pragma unroll
            for (int nt = 0; nt < 8; ++nt) {
                const int lc = moff + nt * 8 + 2 * qc;
                if (lc     > lr0) sacc[nt][0] = -1e30f;
                if (lc + 1 > lr0) sacc[nt][1] = -1e30f;
                if (lc     > lr1) sacc[nt][2] = -1e30f;
                if (lc + 1 > lr1) sacc[nt][3] = -1e30f;
            }
        }

        // ---- in-register online softmax ----
        float mx0 = -1e30f, mx1 = -1e30f;
#pragma unroll
        for (int nt = 0; nt < 8; ++nt) {
            mx0 = fmaxf(mx0, fmaxf(sacc[nt][0], sacc[nt][1]));
            mx1 = fmaxf(mx1, fmaxf(sacc[nt][2], sacc[nt][3]));
        }
        mx0 = fmaxf(mx0, __shfl_xor_sync(0xffffffffu, mx0, 1));
        mx0 = fmaxf(mx0, __shfl_xor_sync(0xffffffffu, mx0, 2));
        mx1 = fmaxf(mx1, __shfl_xor_sync(0xffffffffu, mx1, 1));
        mx1 = fmaxf(mx1, __shfl_xor_sync(0xffffffffu, mx1, 2));

        const float mn0 = fmaxf(m0r, mx0);
        const float mn1 = fmaxf(m1r, mx1);
        const float a0 = __expf(m0r - mn0);
        const float a1 = __expf(m1r - mn1);
        m0r = mn0; m1r = mn1;

        float s0 = 0.0f, s1 = 0.0f;
        uint32_t pf[4][4];
#pragma unroll
        for (int k2 = 0; k2 < 4; ++k2) {
            const float pa0 = __expf(sacc[2 * k2][0] - mn0);
            const float pa1 = __expf(sacc[2 * k2][1] - mn0);
            const float pb0 = __expf(sacc[2 * k2][2] - mn1);
            const float pb1 = __expf(sacc[2 * k2][3] - mn1);
            const float pc0 = __expf(sacc[2 * k2 + 1][0] - mn0);
            const float pc1 = __expf(sacc[2 * k2 + 1][1] - mn0);
            const float pd0 = __expf(sacc[2 * k2 + 1][2] - mn1);
            const float pd1 = __expf(sacc[2 * k2 + 1][3] - mn1);
            s0 += pa0 + pa1 + pc0 + pc1;
            s1 += pb0 + pb1 + pd0 + pd1;
            pf[k2][0] = pack_h2(pa0, pa1);
            pf[k2][1] = pack_h2(pb0, pb1);
            pf[k2][2] = pack_h2(pc0, pc1);
            pf[k2][3] = pack_h2(pd0, pd1);
        }
        s0 += __shfl_xor_sync(0xffffffffu, s0, 1);
        s0 += __shfl_xor_sync(0xffffffffu, s0, 2);
        s1 += __shfl_xor_sync(0xffffffffu, s1, 1);
        s1 += __shfl_xor_sync(0xffffffffu, s1, 2);
        l0r = l0r * a0 + s0;
        l1r = l1r * a1 + s1;

        // ---- rescale + PV via trans-LDSM from V [s][d] ----
#pragma unroll
        for (int nt = 0; nt < 16; ++nt) {
            oacc[nt][0] *= a0; oacc[nt][1] *= a0;
            oacc[nt][2] *= a1; oacc[nt][3] *= a1;
        }
        {
            const uint32_t vBase = smem_u32(&S.Vs[bufC][lrow][lcol]);
#pragma unroll
            for (int k2 = 0; k2 < 4; ++k2) {
                const uint32_t kOff = (uint32_t)(k2 * 16 * LDK * 2);
#pragma unroll
                for (int nt2 = 0; nt2 < 8; ++nt2) {
                    uint32_t bf[4];
                    ldsm_x4_t(bf, vBase + kOff + (uint32_t)(nt2 * 16 * 2));
                    mma_f16(oacc[2 * nt2    ], pf[k2], bf[0], bf[1]);
                    mma_f16(oacc[2 * nt2 + 1], pf[k2], bf[2], bf[3]);
                }
            }
        }
        bufC ^= 1;
    }

    // ---- epilogue ----
    {
        const int t0 = b * SEQ + qt * FQT;
        const float inv0 = 1.0f / l0r;
        const float inv1 = 1.0f / l1r;
        const int row0 = t0 + m0 + qr;
#pragma unroll
        for (int nt = 0; nt < 16; ++nt) {
            const int col = h * HEAD_SIZE + nt * 8 + 2 * qc;
            *(__half2*)&g_attnh[(size_t)row0 * HIDDEN + col] =
                __floats2half2_rn(oacc[nt][0] * inv0, oacc[nt][1] * inv0);
            *(__half2*)&g_attnh[(size_t)(row0 + 8) * HIDDEN + col] =
                __floats2half2_rn(oacc[nt][2] * inv1, oacc[nt][3] * inv1);
        }
    }
}

// ============================================================================
// launch
// ============================================================================
extern "C" void kernel_launch(void* const* d_in, const int* in_sizes, int n_in,
                              void* d_out, int out_size)
{
    const float* hidden  = (const float*)d_in[0];
    const float* cosb    = (const float*)d_in[1];
    const float* sinb    = (const float*)d_in[2];
    const float* W_qkv   = (const float*)d_in[3];
    const float* b_qkv   = (const float*)d_in[4];
    const float* W_dense = (const float*)d_in[5];
    const float* b_dense = (const float*)d_in[6];
    float* out = (float*)d_out;

    __half *attnh_ptr, *hidh_ptr, *wqkvh_ptr, *wdenseh_ptr;
    cudaGetSymbolAddress((void**)&attnh_ptr, g_attnh);
    cudaGetSymbolAddress((void**)&hidh_ptr, g_hidh);
    cudaGetSymbolAddress((void**)&wqkvh_ptr, g_wqkvh);
    cudaGetSymbolAddress((void**)&wdenseh_ptr, g_wdenseh);

    cudaFuncSetAttribute(flash_f16_v7, cudaFuncAttributeMaxDynamicSharedMemorySize,
                         (int)sizeof(Flash7Smem));
    cudaFuncSetAttribute(gemm_qkv_rope, cudaFuncAttributeMaxDynamicSharedMemorySize,
                         GEMM_SMEM_BYTES);
    cudaFuncSetAttribute(gemm_dense, cudaFuncAttributeMaxDynamicSharedMemorySize,
                         GEMM_SMEM_BYTES);

    // 0) operand prep: one merged f2h launch
    f2h_all<<<(N4_ALL + 255) / 256, 256>>>(hidden, W_qkv, W_dense);
    // 1) QKV projection with fused bias+RoPE+split epilogue
    gemm_qkv_rope<<<dim3(QKV_N / 128, TOTAL / 128), 256, GEMM_SMEM_BYTES>>>(
        hidh_ptr, wqkvh_ptr, b_qkv, cosb, sinb);
    // 2) causal flash attention v7 (FQT=128)
    flash_f16_v7<<<dim3(SEQ / FQT, NUM_HEADS, BATCH), 256, sizeof(Flash7Smem)>>>();
    // 3) dense projection (fp32 output)
    gemm_dense<<<dim3(HIDDEN / 128, TOTAL / 128), 256, GEMM_SMEM_BYTES>>>(
        attnh_ptr, wdenseh_ptr, b_dense, out);
}